// round 11
// baseline (speedup 1.0000x reference)
#include <cuda_runtime.h>
#include <cuda_bf16.h>
#include <cstdint>

#define P_ 16
#define B_ 4
#define C_ 256
#define N_ 256
#define PB_ 64

typedef __nv_bfloat16 bf16;

// ---------------- gmem scratch ----------------
__device__ __align__(16) float g_corr[(size_t)PB_ * N_ * C_];   // corr[pb][j][d]
__device__ __align__(16) bf16  g_corr_h[(size_t)PB_ * N_ * C_];
__device__ __align__(16) bf16  g_corr_l[(size_t)PB_ * N_ * C_];
__device__ __align__(16) unsigned short g_tf_f16[(size_t)PB_ * C_ * N_];  // temp fp16 [pb][c][i]
__device__ __align__(16) bf16  g_tfT_h[(size_t)PB_ * N_ * C_];  // temp^T split [pb][i][c]
__device__ __align__(16) bf16  g_tfT_l[(size_t)PB_ * N_ * C_];
__device__ __align__(16) float g_wtf[(size_t)PB_ * N_];

// ---------------- helpers ----------------
__device__ __forceinline__ uint32_t smem_u32(const void* p) {
    uint32_t a;
    asm("{ .reg .u64 t; cvta.to.shared.u64 t, %1; cvt.u32.u64 %0, t; }" : "=r"(a) : "l"(p));
    return a;
}
__device__ __forceinline__ void ldm_x4(uint32_t& r0, uint32_t& r1, uint32_t& r2,
                                       uint32_t& r3, uint32_t a) {
    asm volatile("ldmatrix.sync.aligned.m8n8.x4.shared.b16 {%0,%1,%2,%3}, [%4];"
                 : "=r"(r0), "=r"(r1), "=r"(r2), "=r"(r3) : "r"(a));
}
__device__ __forceinline__ void mma16816(float* c, const uint32_t* a,
                                         uint32_t b0, uint32_t b1) {
    asm volatile("mma.sync.aligned.m16n8k16.row.col.f32.bf16.bf16.f32 "
                 "{%0,%1,%2,%3}, {%4,%5,%6,%7}, {%8,%9}, {%0,%1,%2,%3};"
                 : "+f"(c[0]), "+f"(c[1]), "+f"(c[2]), "+f"(c[3])
                 : "r"(a[0]), "r"(a[1]), "r"(a[2]), "r"(a[3]), "r"(b0), "r"(b1));
}
__device__ __forceinline__ void mma16816h(float* c, const uint32_t* a,
                                          uint32_t b0, uint32_t b1) {
    asm volatile("mma.sync.aligned.m16n8k16.row.col.f32.f16.f16.f32 "
                 "{%0,%1,%2,%3}, {%4,%5,%6,%7}, {%8,%9}, {%0,%1,%2,%3};"
                 : "+f"(c[0]), "+f"(c[1]), "+f"(c[2]), "+f"(c[3])
                 : "r"(a[0]), "r"(a[1]), "r"(a[2]), "r"(a[3]), "r"(b0), "r"(b1));
}
__device__ __forceinline__ uint32_t pack_f16(float lo, float hi) {
    uint32_t r;
    asm("cvt.rn.f16x2.f32 %0, %1, %2;" : "=r"(r) : "f"(hi), "f"(lo));
    return r;
}
__device__ __forceinline__ uint32_t pack2_bf16(bf16 lo, bf16 hi) {
    return ((uint32_t)__bfloat16_as_ushort(hi) << 16) | (uint32_t)__bfloat16_as_ushort(lo);
}
__device__ __forceinline__ void cpa16(uint32_t d, const void* s) {
    asm volatile("cp.async.cg.shared.global [%0], [%1], 16;" :: "r"(d), "l"(s));
}
__device__ __forceinline__ void cp_commit() {
    asm volatile("cp.async.commit_group;" ::: "memory");
}
__device__ __forceinline__ void cp_wait1() {
    asm volatile("cp.async.wait_group 1;" ::: "memory");
}
__device__ __forceinline__ void cp_wait0() {
    asm volatile("cp.async.wait_group 0;" ::: "memory");
}

__device__ __forceinline__ float inv_patch(const void* p) {
    if (p == nullptr) return 1.f / 16.f;
    int iv = *(const int*)p;
    if (iv >= 1 && iv <= 65536) return 1.f / (float)iv;
    float fv = __int_as_float(iv);
    if (fv >= 0.5f && fv <= 65536.f) return 1.f / fv;
    return 1.f / 16.f;
}

// ---------------------------------------------------------------------------
// Prep kernels (unchanged, verified)
// ---------------------------------------------------------------------------
__global__ void __launch_bounds__(256) corr_kernel(const float* __restrict__ temp,
                                                   const float* __restrict__ We) {
    __shared__ float sX[16][64];
    __shared__ float sW[64][17];
    const int t = threadIdx.x;
    const int tx = t & 15, ty = t >> 4;
    const int ti = blockIdx.x & 3, td = blockIdx.x >> 2;
    const int pb = blockIdx.y;
    const float* tf = temp + (size_t)pb * C_ * N_;
    const int i0 = ti * 64, d0 = td * 64;

    float acc[4][4];
#pragma unroll
    for (int u = 0; u < 4; u++)
#pragma unroll
        for (int v = 0; v < 4; v++) acc[u][v] = 0.f;

#pragma unroll 1
    for (int kc = 0; kc < 16; kc++) {
        __syncthreads();
#pragma unroll
        for (int r = 0; r < 4; r++) {
            int e = t + r * 256;
            sX[e >> 6][e & 63] = tf[(kc * 16 + (e >> 6)) * N_ + i0 + (e & 63)];
        }
#pragma unroll
        for (int r = 0; r < 4; r++) {
            int e = t + r * 256;
            sW[e >> 4][e & 15] = We[(size_t)(d0 + (e >> 4)) * C_ + kc * 16 + (e & 15)];
        }
        __syncthreads();
#pragma unroll
        for (int cc = 0; cc < 16; cc++) {
            float a[4], bb[4];
#pragma unroll
            for (int u = 0; u < 4; u++) a[u] = sX[cc][tx * 4 + u];
#pragma unroll
            for (int v = 0; v < 4; v++) bb[v] = sW[ty * 4 + v][cc];
#pragma unroll
            for (int u = 0; u < 4; u++)
#pragma unroll
                for (int v = 0; v < 4; v++) acc[u][v] += a[u] * bb[v];
        }
    }
    float* cr = g_corr + (size_t)pb * N_ * C_;
#pragma unroll
    for (int u = 0; u < 4; u++) {
        int i = i0 + tx * 4 + u;
        float4 w4 = make_float4(acc[u][0], acc[u][1], acc[u][2], acc[u][3]);
        *(float4*)&cr[(size_t)i * C_ + d0 + ty * 4] = w4;
    }
}

__device__ __forceinline__ void split4(const float4 x, uint2& uh, uint2& ul) {
    bf16 h0 = __float2bfloat16(x.x), h1 = __float2bfloat16(x.y);
    bf16 h2 = __float2bfloat16(x.z), h3 = __float2bfloat16(x.w);
    bf16 l0 = __float2bfloat16(x.x - __bfloat162float(h0));
    bf16 l1 = __float2bfloat16(x.y - __bfloat162float(h1));
    bf16 l2 = __float2bfloat16(x.z - __bfloat162float(h2));
    bf16 l3 = __float2bfloat16(x.w - __bfloat162float(h3));
    uh = make_uint2(pack2_bf16(h0, h1), pack2_bf16(h2, h3));
    ul = make_uint2(pack2_bf16(l0, l1), pack2_bf16(l2, l3));
}
__global__ void __launch_bounds__(256) split_corr() {
    size_t i = (size_t)blockIdx.x * 256 + threadIdx.x;
    float4 x = ((const float4*)g_corr)[i];
    uint2 uh, ul;
    split4(x, uh, ul);
    ((uint2*)g_corr_h)[i] = uh;
    ((uint2*)g_corr_l)[i] = ul;
}
__global__ void __launch_bounds__(256) cvt_tf_f16(const float* __restrict__ temp) {
    size_t i = (size_t)blockIdx.x * 256 + threadIdx.x;
    float4 x = ((const float4*)temp)[i];
    uint32_t a = pack_f16(x.x, x.y);
    uint32_t b = pack_f16(x.z, x.w);
    ((uint2*)g_tf_f16)[i] = make_uint2(a, b);
}
__global__ void __launch_bounds__(256) transpose_split(const float* __restrict__ temp) {
    __shared__ float tile[32][33];
    const int pb = blockIdx.z;
    const int i0 = blockIdx.x * 32, c0 = blockIdx.y * 32;
    const int tx = threadIdx.x & 31, ty = threadIdx.x >> 5;
    const float* src = temp + (size_t)pb * C_ * N_;
#pragma unroll
    for (int k = 0; k < 4; k++) {
        int c = c0 + ty + k * 8;
        tile[ty + k * 8][tx] = src[(size_t)c * N_ + i0 + tx];
    }
    __syncthreads();
#pragma unroll
    for (int k = 0; k < 4; k++) {
        int i = i0 + ty + k * 8;
        float x = tile[tx][ty + k * 8];
        size_t o = (size_t)pb * N_ * C_ + (size_t)i * C_ + c0 + tx;
        bf16 hh = __float2bfloat16(x);
        g_tfT_h[o] = hh;
        g_tfT_l[o] = __float2bfloat16(x - __bfloat162float(hh));
    }
}
__global__ void __launch_bounds__(256) wtf_kernel(const float* __restrict__ temp,
                                                  const float* __restrict__ Wg) {
    __shared__ float sWg[256];
    const int pb = blockIdx.x, i = threadIdx.x;
    sWg[i] = Wg[i];
    __syncthreads();
    const float* src = temp + (size_t)pb * C_ * N_;
    float s = 0.f;
#pragma unroll 8
    for (int c = 0; c < 256; c++) s += src[(size_t)c * N_ + i] * sWg[c];
    g_wtf[(size_t)pb * N_ + i] = s;
}

// ---------------------------------------------------------------------------
// Fused kernel. 256 CTAs = 64 pb x 4 j-tiles(64). 256 threads, 2 CTAs/SM.
// SMEM per CTA (bytes):
//   [0,40960)        S0: GEMM1 buf0 = B(tfT) 32K + A(corr) 8K ; GEMM2 tf buf0 in B-part
//   [40960,81920)    S1: buf1 (same layout); sSum/sG live in S1.A slack during softmax
//   [81920,114688)   P fp16: 4 i-chunks x (64 rows x 128B)
//   [114688,115712)  sWtf (256 floats)
// ---------------------------------------------------------------------------
#define SBUF 40960
#define AOFF 32768
#define PBASE 81920
#define SWTF 114688
#define SSUM (SBUF + AOFF)          /* S1.A slack */
#define SGG  (SBUF + AOFF + 512)
#define SMEM_TOTAL 115712

__device__ __forceinline__ void issue_g1(uint32_t sb, int buf, int t,
                                         int qb, int pb, int j0, int kc) {
    // B: tfT rows 0..255, d-chunk kc (32 wide), packed [64B hi | 64B lo]
    const size_t bo = (size_t)qb * 65536 + (size_t)t * 256 + (size_t)kc * 32;
    const uint32_t dst = sb + buf * SBUF + t * 128;
    const uint32_t sw = (uint32_t)((t & 7) << 4);
#pragma unroll
    for (int v = 0; v < 4; v++)
        cpa16(dst + (((uint32_t)(v * 16)) ^ sw), g_tfT_h + bo + v * 8);
#pragma unroll
    for (int v = 0; v < 4; v++)
        cpa16(dst + (((uint32_t)(64 + v * 16)) ^ sw), g_tfT_l + bo + v * 8);
    // A: corr rows j0..j0+63, 2 cpa16 per thread (512 total)
#pragma unroll
    for (int u = 0; u < 2; u++) {
        const int idx = t * 2 + u;
        const int row = idx >> 3, v = idx & 7;
        const bf16* srcp = (v < 4 ? g_corr_h : g_corr_l) +
                           ((size_t)pb * 65536 + (size_t)(j0 + row) * 256 +
                            (size_t)kc * 32 + (size_t)(v & 3) * 8);
        const uint32_t d = sb + buf * SBUF + AOFF + row * 128 +
                           (((uint32_t)(v * 16)) ^ ((uint32_t)((row & 7) << 4)));
        cpa16(d, srcp);
    }
}

// GEMM2: stage tf fp16 chunk kc (64 i = 128B per c-row) into S{buf}.B
__device__ __forceinline__ void issue_g2(uint32_t sb, int buf, int t, int qb, int kc) {
    const unsigned short* src = g_tf_f16 + (size_t)qb * 65536 + (size_t)t * 256 + (size_t)kc * 64;
    const uint32_t dst = sb + buf * SBUF + t * 128;
    const uint32_t sw = (uint32_t)((t & 7) << 4);
#pragma unroll
    for (int v = 0; v < 8; v++)
        cpa16(dst + (((uint32_t)(v * 16)) ^ sw), src + v * 8);
}

__global__ void __launch_bounds__(256, 2)
fused_mma(const void* __restrict__ pnp, float* __restrict__ out) {
    extern __shared__ char smd[];
    const uint32_t sb = smem_u32(smd);
    float* sWtf = (float*)(smd + SWTF);
    float* sSum = (float*)(smd + SSUM);   // [2][64]
    float* sG   = (float*)(smd + SGG);    // [2][64]

    const int t = threadIdx.x;
    const int w = t >> 5, lane = t & 31;
    const int jt = blockIdx.x & 3;
    const int pb = blockIdx.x >> 2;
    const int b = pb & 3;
    const int j0 = jt * 64;

    const int wj = w >> 1, wi = w & 1;      // GEMM1: 4 j-warps(16j) x 2 i-warps(128i)
    const int wc = w >> 1, wj2 = w & 1;     // GEMM2: 4 c-warps(64c) x 2 j-warps(32j)
    const float invp = inv_patch(pnp);

    const int a_row_off = ((lane >> 3) & 1) * 8 + (lane & 7);
    const int a_col_off = ((lane >> 4) & 1) * 16;
    const int b_row_off = ((lane >> 4) & 1) * 8 + (lane & 7);
    const int b_col_off = ((lane >> 3) & 1) * 16;

    issue_g1(sb, 0, t, 0 * B_ + b, pb, j0, 0);
    cp_commit();

#pragma unroll 1
    for (int q = 0; q < P_; q++) {
        const int qb = q * B_ + b;
        sWtf[t] = g_wtf[(size_t)qb * N_ + t];

        // ========= GEMM1: logits[64j x 256i], bf16 3-term; warp: 16j x 128i ==
        float acc1[16][4];
#pragma unroll
        for (int n = 0; n < 16; n++)
#pragma unroll
            for (int x = 0; x < 4; x++) acc1[n][x] = 0.f;

#pragma unroll 1
        for (int kc = 0; kc < 8; kc++) {
            if (kc < 7) { issue_g1(sb, (kc + 1) & 1, t, qb, pb, j0, kc + 1); cp_commit(); }
            if (kc < 7) cp_wait1(); else cp_wait0();
            __syncthreads();
            const uint32_t bB = sb + (kc & 1) * SBUF;
            const uint32_t bA = bB + AOFF;
#pragma unroll
            for (int s = 0; s < 2; s++) {
                uint32_t ah[4], al[4];
                {
                    const int ar = 16 * wj + a_row_off;
                    const uint32_t sw = (uint32_t)((ar & 7) << 4);
                    const uint32_t ad = bA + ar * 128;
                    ldm_x4(ah[0], ah[1], ah[2], ah[3],
                           ad + (((uint32_t)(s * 32 + a_col_off)) ^ sw));
                    ldm_x4(al[0], al[1], al[2], al[3],
                           ad + (((uint32_t)(64 + s * 32 + a_col_off)) ^ sw));
                }
#pragma unroll
                for (int np = 0; np < 8; np++) {
                    const int br = 128 * wi + np * 16 + b_row_off;
                    const uint32_t sw = (uint32_t)((br & 7) << 4);
                    const uint32_t bd = bB + br * 128;
                    uint32_t bh[4], bl[4];
                    ldm_x4(bh[0], bh[1], bh[2], bh[3],
                           bd + (((uint32_t)(s * 32 + b_col_off)) ^ sw));
                    ldm_x4(bl[0], bl[1], bl[2], bl[3],
                           bd + (((uint32_t)(64 + s * 32 + b_col_off)) ^ sw));
                    float* e = acc1[2 * np];
                    float* o = acc1[2 * np + 1];
                    mma16816(e, ah, bh[0], bh[1]);
                    mma16816(o, ah, bh[2], bh[3]);
                    mma16816(e, ah, bl[0], bl[1]);
                    mma16816(o, ah, bl[2], bl[3]);
                    mma16816(e, al, bh[0], bh[1]);
                    mma16816(o, al, bh[2], bh[3]);
                }
            }
            __syncthreads();
        }

        // prefetch GEMM2 chunk 0 into S0.B (lands during softmax)
        issue_g2(sb, 0, t, qb, 0);
        cp_commit();

        // ============ softmax (unnorm, shift 40) + gate fold + P fp16 =======
        {
            float s1 = 0.f, g1 = 0.f, s2 = 0.f, g2 = 0.f;
#pragma unroll
            for (int nt = 0; nt < 16; nt++) {
                const int col = 128 * wi + nt * 8 + (lane & 3) * 2;
                float2 wv = *(float2*)&sWtf[col];
                float e0 = __expf(acc1[nt][0] - 40.f);
                float e1 = __expf(acc1[nt][1] - 40.f);
                float e2 = __expf(acc1[nt][2] - 40.f);
                float e3 = __expf(acc1[nt][3] - 40.f);
                acc1[nt][0] = e0; acc1[nt][1] = e1;
                acc1[nt][2] = e2; acc1[nt][3] = e3;
                s1 += e0 + e1; g1 += e0 * wv.x + e1 * wv.y;
                s2 += e2 + e3; g2 += e2 * wv.x + e3 * wv.y;
            }
#pragma unroll
            for (int o = 1; o <= 2; o <<= 1) {
                s1 += __shfl_xor_sync(0xffffffffu, s1, o);
                g1 += __shfl_xor_sync(0xffffffffu, g1, o);
                s2 += __shfl_xor_sync(0xffffffffu, s2, o);
                g2 += __shfl_xor_sync(0xffffffffu, g2, o);
            }
            if ((lane & 3) == 0) {
                const int r1 = 16 * wj + (lane >> 2);
                sSum[wi * 64 + r1] = s1;     sG[wi * 64 + r1] = g1;
                sSum[wi * 64 + r1 + 8] = s2; sG[wi * 64 + r1 + 8] = g2;
            }
            __syncthreads();
            float sc[2];
#pragma unroll
            for (int h = 0; h < 2; h++) {
                const int r = 16 * wj + (lane >> 2) + 8 * h;
                const float tot = sSum[r] + sSum[64 + r];
                const float gt  = sG[r] + sG[64 + r];
                sc[h] = (1.f / (1.f + __expf(-gt / tot))) / tot;
            }
            const int r1 = 16 * wj + (lane >> 2);
            const int r2 = r1 + 8;
            const uint32_t sw1 = (uint32_t)((r1 & 7) << 4);
            const uint32_t sw2 = (uint32_t)((r2 & 7) << 4);
#pragma unroll
            for (int nt = 0; nt < 16; nt++) {
                const int ch = 2 * wi + (nt >> 3);
                const uint32_t off = (uint32_t)((nt & 7) * 16 + (lane & 3) * 4);
                char* base = smd + PBASE + ch * 8192;
                uint32_t hu = pack_f16(acc1[nt][0] * sc[0], acc1[nt][1] * sc[0]);
                *(uint32_t*)(base + r1 * 128 + (off ^ sw1)) = hu;
                hu = pack_f16(acc1[nt][2] * sc[1], acc1[nt][3] * sc[1]);
                *(uint32_t*)(base + r2 * 128 + (off ^ sw2)) = hu;
            }
        }

        // ===== GEMM2: att[256c x 64j] = tf_f16 . P^T; warp: 64c x 32j ========
        float acc2[4][4][4];
#pragma unroll
        for (int m = 0; m < 4; m++)
#pragma unroll
            for (int n = 0; n < 4; n++)
#pragma unroll
                for (int x = 0; x < 4; x++) acc2[m][n][x] = 0.f;

#pragma unroll 1
        for (int kc = 0; kc < 4; kc++) {
            if (kc < 3) { issue_g2(sb, (kc + 1) & 1, t, qb, kc + 1); cp_commit(); }
            if (kc < 3) cp_wait1(); else cp_wait0();
            __syncthreads();
            const uint32_t bA2 = sb + (kc & 1) * SBUF;
            const uint32_t pB = sb + PBASE + kc * 8192;
#pragma unroll
            for (int s = 0; s < 4; s++) {
                uint32_t ah[4][4];
#pragma unroll
                for (int mt = 0; mt < 4; mt++) {
                    const int ar = 64 * wc + 16 * mt + a_row_off;
                    const uint32_t sw = (uint32_t)((ar & 7) << 4);
                    ldm_x4(ah[mt][0], ah[mt][1], ah[mt][2], ah[mt][3],
                           bA2 + ar * 128 + (((uint32_t)(s * 32 + a_col_off)) ^ sw));
                }
#pragma unroll
                for (int np = 0; np < 2; np++) {
                    const int br = 32 * wj2 + np * 16 + b_row_off;
                    const uint32_t sw = (uint32_t)((br & 7) << 4);
                    uint32_t bh[4];
                    ldm_x4(bh[0], bh[1], bh[2], bh[3],
                           pB + br * 128 + (((uint32_t)(s * 32 + b_col_off)) ^ sw));
#pragma unroll
                    for (int mt = 0; mt < 4; mt++) {
                        mma16816h(acc2[mt][2 * np],     ah[mt], bh[0], bh[1]);
                        mma16816h(acc2[mt][2 * np + 1], ah[mt], bh[2], bh[3]);
                    }
                }
            }
            __syncthreads();
        }

        // prefetch next q's GEMM1 chunk 0 (lands during epilogue)
        if (q < P_ - 1) { issue_g1(sb, 0, t, qb + B_, pb, j0, 0); cp_commit(); }

        // ===================== epilogue: RMW accumulate ======================
        {
            float* ob = out + (size_t)pb * 65536 + j0 + 32 * wj2;
#pragma unroll
            for (int mt = 0; mt < 4; mt++) {
#pragma unroll
                for (int h = 0; h < 2; h++) {
                    const int c = 64 * wc + 16 * mt + 8 * h + (lane >> 2);
                    float* rowp = ob + (size_t)c * 256;
#pragma unroll
                    for (int nt = 0; nt < 4; nt++) {
                        float v0 = acc2[mt][nt][2 * h];
                        float v1 = acc2[mt][nt][2 * h + 1];
                        float2* pp = (float2*)(rowp + nt * 8 + (lane & 3) * 2);
                        if (q == 0) {
                            *pp = make_float2(v0, v1);
                        } else {
                            float2 o = *pp;
                            o.x += v0; o.y += v1;
                            if (q == P_ - 1) { o.x *= invp; o.y *= invp; }
                            *pp = o;
                        }
                    }
                }
            }
        }
    }
}

// ---------------------------------------------------------------------------
extern "C" void kernel_launch(void* const* d_in, const int* in_sizes, int n_in,
                              void* d_out, int out_size) {
    const float* temp = (const float*)d_in[0];
    const float* We   = (const float*)d_in[1];
    const float* Wg   = (const float*)d_in[2];
    const void*  pn   = (n_in > 3) ? d_in[3] : nullptr;
    float* out = (float*)d_out;

    const int n4 = (PB_ * C_ * N_) / 4;

    corr_kernel<<<dim3(16, 64), 256>>>(temp, We);
    split_corr<<<n4 / 256, 256>>>();
    cvt_tf_f16<<<n4 / 256, 256>>>(temp);
    transpose_split<<<dim3(8, 8, 64), 256>>>(temp);
    wtf_kernel<<<64, 256>>>(temp, Wg);

    cudaFuncSetAttribute(fused_mma, cudaFuncAttributeMaxDynamicSharedMemorySize, SMEM_TOTAL);
    fused_mma<<<256, 256, SMEM_TOTAL>>>(pn, out);
}

// round 12
// speedup vs baseline: 1.2598x; 1.2598x over previous
#include <cuda_runtime.h>
#include <cuda_bf16.h>
#include <cstdint>

#define P_ 16
#define B_ 4
#define C_ 256
#define N_ 256
#define PB_ 64

typedef __nv_bfloat16 bf16;

// ---------------- gmem scratch ----------------
__device__ __align__(16) float g_corr[(size_t)PB_ * N_ * C_];   // corr[pb][j][d]
__device__ __align__(16) bf16  g_corr_h[(size_t)PB_ * N_ * C_];
__device__ __align__(16) bf16  g_corr_l[(size_t)PB_ * N_ * C_];
__device__ __align__(16) unsigned short g_tf_f16[(size_t)PB_ * C_ * N_];  // temp fp16 [pb][c][i]
__device__ __align__(16) bf16  g_tfT_h[(size_t)PB_ * N_ * C_];  // temp^T split [pb][i][c]
__device__ __align__(16) bf16  g_tfT_l[(size_t)PB_ * N_ * C_];
__device__ __align__(16) float g_wtf[(size_t)PB_ * N_];

// ---------------- helpers ----------------
__device__ __forceinline__ uint32_t smem_u32(const void* p) {
    uint32_t a;
    asm("{ .reg .u64 t; cvta.to.shared.u64 t, %1; cvt.u32.u64 %0, t; }" : "=r"(a) : "l"(p));
    return a;
}
__device__ __forceinline__ void ldm_x4(uint32_t& r0, uint32_t& r1, uint32_t& r2,
                                       uint32_t& r3, uint32_t a) {
    asm volatile("ldmatrix.sync.aligned.m8n8.x4.shared.b16 {%0,%1,%2,%3}, [%4];"
                 : "=r"(r0), "=r"(r1), "=r"(r2), "=r"(r3) : "r"(a));
}
__device__ __forceinline__ void mma16816(float* c, const uint32_t* a,
                                         uint32_t b0, uint32_t b1) {
    asm volatile("mma.sync.aligned.m16n8k16.row.col.f32.bf16.bf16.f32 "
                 "{%0,%1,%2,%3}, {%4,%5,%6,%7}, {%8,%9}, {%0,%1,%2,%3};"
                 : "+f"(c[0]), "+f"(c[1]), "+f"(c[2]), "+f"(c[3])
                 : "r"(a[0]), "r"(a[1]), "r"(a[2]), "r"(a[3]), "r"(b0), "r"(b1));
}
__device__ __forceinline__ void mma16816h(float* c, const uint32_t* a,
                                          uint32_t b0, uint32_t b1) {
    asm volatile("mma.sync.aligned.m16n8k16.row.col.f32.f16.f16.f32 "
                 "{%0,%1,%2,%3}, {%4,%5,%6,%7}, {%8,%9}, {%0,%1,%2,%3};"
                 : "+f"(c[0]), "+f"(c[1]), "+f"(c[2]), "+f"(c[3])
                 : "r"(a[0]), "r"(a[1]), "r"(a[2]), "r"(a[3]), "r"(b0), "r"(b1));
}
__device__ __forceinline__ uint32_t pack_f16(float lo, float hi) {
    uint32_t r;
    asm("cvt.rn.f16x2.f32 %0, %1, %2;" : "=r"(r) : "f"(hi), "f"(lo));
    return r;
}
__device__ __forceinline__ uint32_t pack2_bf16(bf16 lo, bf16 hi) {
    return ((uint32_t)__bfloat16_as_ushort(hi) << 16) | (uint32_t)__bfloat16_as_ushort(lo);
}
__device__ __forceinline__ void cpa16(uint32_t d, const void* s) {
    asm volatile("cp.async.cg.shared.global [%0], [%1], 16;" :: "r"(d), "l"(s));
}
__device__ __forceinline__ void cp_commit() {
    asm volatile("cp.async.commit_group;" ::: "memory");
}
__device__ __forceinline__ void cp_wait1() {
    asm volatile("cp.async.wait_group 1;" ::: "memory");
}
__device__ __forceinline__ void cp_wait0() {
    asm volatile("cp.async.wait_group 0;" ::: "memory");
}

__device__ __forceinline__ float inv_patch(const void* p) {
    if (p == nullptr) return 1.f / 16.f;
    int iv = *(const int*)p;
    if (iv >= 1 && iv <= 65536) return 1.f / (float)iv;
    float fv = __int_as_float(iv);
    if (fv >= 0.5f && fv <= 65536.f) return 1.f / fv;
    return 1.f / 16.f;
}

// ---------------------------------------------------------------------------
// Prep kernels (unchanged, verified)
// ---------------------------------------------------------------------------
__global__ void __launch_bounds__(256) corr_kernel(const float* __restrict__ temp,
                                                   const float* __restrict__ We) {
    __shared__ float sX[16][64];
    __shared__ float sW[64][17];
    const int t = threadIdx.x;
    const int tx = t & 15, ty = t >> 4;
    const int ti = blockIdx.x & 3, td = blockIdx.x >> 2;
    const int pb = blockIdx.y;
    const float* tf = temp + (size_t)pb * C_ * N_;
    const int i0 = ti * 64, d0 = td * 64;

    float acc[4][4];
#pragma unroll
    for (int u = 0; u < 4; u++)
#pragma unroll
        for (int v = 0; v < 4; v++) acc[u][v] = 0.f;

#pragma unroll 1
    for (int kc = 0; kc < 16; kc++) {
        __syncthreads();
#pragma unroll
        for (int r = 0; r < 4; r++) {
            int e = t + r * 256;
            sX[e >> 6][e & 63] = tf[(kc * 16 + (e >> 6)) * N_ + i0 + (e & 63)];
        }
#pragma unroll
        for (int r = 0; r < 4; r++) {
            int e = t + r * 256;
            sW[e >> 4][e & 15] = We[(size_t)(d0 + (e >> 4)) * C_ + kc * 16 + (e & 15)];
        }
        __syncthreads();
#pragma unroll
        for (int cc = 0; cc < 16; cc++) {
            float a[4], bb[4];
#pragma unroll
            for (int u = 0; u < 4; u++) a[u] = sX[cc][tx * 4 + u];
#pragma unroll
            for (int v = 0; v < 4; v++) bb[v] = sW[ty * 4 + v][cc];
#pragma unroll
            for (int u = 0; u < 4; u++)
#pragma unroll
                for (int v = 0; v < 4; v++) acc[u][v] += a[u] * bb[v];
        }
    }
    float* cr = g_corr + (size_t)pb * N_ * C_;
#pragma unroll
    for (int u = 0; u < 4; u++) {
        int i = i0 + tx * 4 + u;
        float4 w4 = make_float4(acc[u][0], acc[u][1], acc[u][2], acc[u][3]);
        *(float4*)&cr[(size_t)i * C_ + d0 + ty * 4] = w4;
    }
}

__device__ __forceinline__ void split4(const float4 x, uint2& uh, uint2& ul) {
    bf16 h0 = __float2bfloat16(x.x), h1 = __float2bfloat16(x.y);
    bf16 h2 = __float2bfloat16(x.z), h3 = __float2bfloat16(x.w);
    bf16 l0 = __float2bfloat16(x.x - __bfloat162float(h0));
    bf16 l1 = __float2bfloat16(x.y - __bfloat162float(h1));
    bf16 l2 = __float2bfloat16(x.z - __bfloat162float(h2));
    bf16 l3 = __float2bfloat16(x.w - __bfloat162float(h3));
    uh = make_uint2(pack2_bf16(h0, h1), pack2_bf16(h2, h3));
    ul = make_uint2(pack2_bf16(l0, l1), pack2_bf16(l2, l3));
}
__global__ void __launch_bounds__(256) split_corr() {
    size_t i = (size_t)blockIdx.x * 256 + threadIdx.x;
    float4 x = ((const float4*)g_corr)[i];
    uint2 uh, ul;
    split4(x, uh, ul);
    ((uint2*)g_corr_h)[i] = uh;
    ((uint2*)g_corr_l)[i] = ul;
}
__global__ void __launch_bounds__(256) cvt_tf_f16(const float* __restrict__ temp) {
    size_t i = (size_t)blockIdx.x * 256 + threadIdx.x;
    float4 x = ((const float4*)temp)[i];
    uint32_t a = pack_f16(x.x, x.y);
    uint32_t b = pack_f16(x.z, x.w);
    ((uint2*)g_tf_f16)[i] = make_uint2(a, b);
}
__global__ void __launch_bounds__(256) transpose_split(const float* __restrict__ temp) {
    __shared__ float tile[32][33];
    const int pb = blockIdx.z;
    const int i0 = blockIdx.x * 32, c0 = blockIdx.y * 32;
    const int tx = threadIdx.x & 31, ty = threadIdx.x >> 5;
    const float* src = temp + (size_t)pb * C_ * N_;
#pragma unroll
    for (int k = 0; k < 4; k++) {
        int c = c0 + ty + k * 8;
        tile[ty + k * 8][tx] = src[(size_t)c * N_ + i0 + tx];
    }
    __syncthreads();
#pragma unroll
    for (int k = 0; k < 4; k++) {
        int i = i0 + ty + k * 8;
        float x = tile[tx][ty + k * 8];
        size_t o = (size_t)pb * N_ * C_ + (size_t)i * C_ + c0 + tx;
        bf16 hh = __float2bfloat16(x);
        g_tfT_h[o] = hh;
        g_tfT_l[o] = __float2bfloat16(x - __bfloat162float(hh));
    }
}
__global__ void __launch_bounds__(256) wtf_kernel(const float* __restrict__ temp,
                                                  const float* __restrict__ Wg) {
    __shared__ float sWg[256];
    const int pb = blockIdx.x, i = threadIdx.x;
    sWg[i] = Wg[i];
    __syncthreads();
    const float* src = temp + (size_t)pb * C_ * N_;
    float s = 0.f;
#pragma unroll 8
    for (int c = 0; c < 256; c++) s += src[(size_t)c * N_ + i] * sWg[c];
    g_wtf[(size_t)pb * N_ + i] = s;
}

// ---------------------------------------------------------------------------
// Fused kernel. 128 CTAs = 64 pb x 2 j-tiles(128). 512 threads (16 warps).
// SMEM layout identical to R9 (validated): two 48K stage bufs, P fp16 64K, misc.
// ---------------------------------------------------------------------------
#define STGB 49152
#define G2B  32768
#define PBASE 98304
#define SWTF 163840
#define SSUM 164864
#define SGG  165888
#define SMEM_TOTAL 166912
#define NT 512

// GEMM1 staging, 512 threads: B = tfT 256 rows x [64B hi | 64B lo]; A = corr
// 128 rows x [64B hi | 64B lo]. 6 cpa16 per thread.
__device__ __forceinline__ void issue_g1(uint32_t sb, int buf, int t,
                                         int qb, int pb, int j0, int kc) {
    {   // B: thread covers half a row (hi or lo 64B)
        const int row = t >> 1, half = t & 1;
        const bf16* src = (half ? g_tfT_l : g_tfT_h) +
                          ((size_t)qb * 65536 + (size_t)row * 256 + (size_t)kc * 32);
        const uint32_t dst = sb + buf * STGB + row * 128;
        const uint32_t sw = (uint32_t)((row & 7) << 4);
#pragma unroll
        for (int v = 0; v < 4; v++)
            cpa16(dst + (((uint32_t)(half * 64 + v * 16)) ^ sw), src + v * 8);
    }
    {   // A: 1024 16B-chunks over 512 threads -> 2 each
#pragma unroll
        for (int u = 0; u < 2; u++) {
            const int idx = t * 2 + u;
            const int row = idx >> 3, v = idx & 7;
            const bf16* srcp = (v < 4 ? g_corr_h : g_corr_l) +
                               ((size_t)pb * 65536 + (size_t)(j0 + row) * 256 +
                                (size_t)kc * 32 + (size_t)(v & 3) * 8);
            const uint32_t d = sb + buf * STGB + 32768 + row * 128 +
                               (((uint32_t)(v * 16)) ^ ((uint32_t)((row & 7) << 4)));
            cpa16(d, srcp);
        }
    }
}

// GEMM2 staging: tf fp16 chunk kc (256 rows x 128B), 4 cpa16 per thread
__device__ __forceinline__ void issue_g2(uint32_t sb, int buf, int t, int qb, int kc) {
    const int row = t >> 1, half = t & 1;
    const unsigned short* src = g_tf_f16 + (size_t)qb * 65536 + (size_t)row * 256 +
                                (size_t)kc * 64 + (size_t)half * 32;
    const uint32_t dst = sb + buf * G2B + row * 128;
    const uint32_t sw = (uint32_t)((row & 7) << 4);
#pragma unroll
    for (int v = 0; v < 4; v++)
        cpa16(dst + (((uint32_t)(half * 64 + v * 16)) ^ sw), src + v * 8);
}

__global__ void __launch_bounds__(NT, 1)
fused_mma(const void* __restrict__ pnp, float* __restrict__ out) {
    extern __shared__ char smd[];
    const uint32_t sb = smem_u32(smd);
    float* sWtf = (float*)(smd + SWTF);
    float* sSum = (float*)(smd + SSUM);   // [2][128]
    float* sG   = (float*)(smd + SGG);    // [2][128]

    const int t = threadIdx.x;
    const int w = t >> 5, lane = t & 31;
    const int jt = blockIdx.x & 1;
    const int pb = blockIdx.x >> 1;
    const int b = pb & 3;
    const int j0 = jt * 128;

    const int wj = w >> 1, wi = w & 1;      // GEMM1: 8 j-warps(16j) x 2 i-warps(128i)
    const int wc = w >> 1, wj2 = w & 1;     // GEMM2: 8 c-warps(32c) x 2 j-warps(64j)
    const float invp = inv_patch(pnp);

    const int a_row_off = ((lane >> 3) & 1) * 8 + (lane & 7);
    const int a_col_off = ((lane >> 4) & 1) * 16;
    const int b_row_off = ((lane >> 4) & 1) * 8 + (lane & 7);
    const int b_col_off = ((lane >> 3) & 1) * 16;

    issue_g1(sb, 0, t, 0 * B_ + b, pb, j0, 0);
    cp_commit();

#pragma unroll 1
    for (int q = 0; q < P_; q++) {
        const int qb = q * B_ + b;
        if (t < 256) sWtf[t] = g_wtf[(size_t)qb * N_ + t];

        // ===== GEMM1: logits[128j x 256i], bf16 3-term; warp: 16j x 128i =====
        float acc1[16][4];
#pragma unroll
        for (int n = 0; n < 16; n++)
#pragma unroll
            for (int x = 0; x < 4; x++) acc1[n][x] = 0.f;

#pragma unroll 1
        for (int kc = 0; kc < 8; kc++) {
            if (kc < 7) { issue_g1(sb, (kc + 1) & 1, t, qb, pb, j0, kc + 1); cp_commit(); }
            if (kc < 7) cp_wait1(); else cp_wait0();
            __syncthreads();
            const uint32_t bB = sb + (kc & 1) * STGB;
            const uint32_t bA = bB + 32768;
#pragma unroll
            for (int s = 0; s < 2; s++) {
                uint32_t ah[4], al[4];
                {
                    const int ar = 16 * wj + a_row_off;
                    const uint32_t sw = (uint32_t)((ar & 7) << 4);
                    const uint32_t ad = bA + ar * 128;
                    ldm_x4(ah[0], ah[1], ah[2], ah[3],
                           ad + (((uint32_t)(s * 32 + a_col_off)) ^ sw));
                    ldm_x4(al[0], al[1], al[2], al[3],
                           ad + (((uint32_t)(64 + s * 32 + a_col_off)) ^ sw));
                }
#pragma unroll
                for (int np = 0; np < 8; np++) {
                    const int br = 128 * wi + np * 16 + b_row_off;
                    const uint32_t sw = (uint32_t)((br & 7) << 4);
                    const uint32_t bd = bB + br * 128;
                    uint32_t bh[4], bl[4];
                    ldm_x4(bh[0], bh[1], bh[2], bh[3],
                           bd + (((uint32_t)(s * 32 + b_col_off)) ^ sw));
                    ldm_x4(bl[0], bl[1], bl[2], bl[3],
                           bd + (((uint32_t)(64 + s * 32 + b_col_off)) ^ sw));
                    float* e = acc1[2 * np];
                    float* o = acc1[2 * np + 1];
                    mma16816(e, ah, bh[0], bh[1]);
                    mma16816(o, ah, bh[2], bh[3]);
                    mma16816(e, ah, bl[0], bl[1]);
                    mma16816(o, ah, bl[2], bl[3]);
                    mma16816(e, al, bh[0], bh[1]);
                    mma16816(o, al, bh[2], bh[3]);
                }
            }
            __syncthreads();
        }

        // prefetch GEMM2 chunk 0 (lands during softmax)
        issue_g2(sb, 0, t, qb, 0);
        cp_commit();

        // ============ softmax (unnorm, shift 40) + gate fold + P fp16 =======
        {
            float s1 = 0.f, g1 = 0.f, s2 = 0.f, g2 = 0.f;
#pragma unroll
            for (int nt = 0; nt < 16; nt++) {
                const int col = 128 * wi + nt * 8 + (lane & 3) * 2;
                float2 wv = *(float2*)&sWtf[col];
                float e0 = __expf(acc1[nt][0] - 40.f);
                float e1 = __expf(acc1[nt][1] - 40.f);
                float e2 = __expf(acc1[nt][2] - 40.f);
                float e3 = __expf(acc1[nt][3] - 40.f);
                acc1[nt][0] = e0; acc1[nt][1] = e1;
                acc1[nt][2] = e2; acc1[nt][3] = e3;
                s1 += e0 + e1; g1 += e0 * wv.x + e1 * wv.y;
                s2 += e2 + e3; g2 += e2 * wv.x + e3 * wv.y;
            }
#pragma unroll
            for (int o = 1; o <= 2; o <<= 1) {
                s1 += __shfl_xor_sync(0xffffffffu, s1, o);
                g1 += __shfl_xor_sync(0xffffffffu, g1, o);
                s2 += __shfl_xor_sync(0xffffffffu, s2, o);
                g2 += __shfl_xor_sync(0xffffffffu, g2, o);
            }
            if ((lane & 3) == 0) {
                const int r1 = 16 * wj + (lane >> 2);
                sSum[wi * 128 + r1] = s1;     sG[wi * 128 + r1] = g1;
                sSum[wi * 128 + r1 + 8] = s2; sG[wi * 128 + r1 + 8] = g2;
            }
            __syncthreads();
            float sc[2];
#pragma unroll
            for (int h = 0; h < 2; h++) {
                const int r = 16 * wj + (lane >> 2) + 8 * h;
                const float tot = sSum[r] + sSum[128 + r];
                const float gt  = sG[r] + sG[128 + r];
                sc[h] = (1.f / (1.f + __expf(-gt / tot))) / tot;
            }
            const int r1 = 16 * wj + (lane >> 2);
            const int r2 = r1 + 8;
            const uint32_t sw1 = (uint32_t)((r1 & 7) << 4);
            const uint32_t sw2 = (uint32_t)((r2 & 7) << 4);
#pragma unroll
            for (int nt = 0; nt < 16; nt++) {
                const int ch = 2 * wi + (nt >> 3);
                const uint32_t off = (uint32_t)((nt & 7) * 16 + (lane & 3) * 4);
                char* base = smd + PBASE + ch * 16384;
                uint32_t hu = pack_f16(acc1[nt][0] * sc[0], acc1[nt][1] * sc[0]);
                *(uint32_t*)(base + r1 * 128 + (off ^ sw1)) = hu;
                hu = pack_f16(acc1[nt][2] * sc[1], acc1[nt][3] * sc[1]);
                *(uint32_t*)(base + r2 * 128 + (off ^ sw2)) = hu;
            }
        }

        // ===== GEMM2: att[256c x 128j] = tf_f16 . P^T; warp: 32c x 64j =======
        float acc2[2][8][4];
#pragma unroll
        for (int m = 0; m < 2; m++)
#pragma unroll
            for (int n = 0; n < 8; n++)
#pragma unroll
                for (int x = 0; x < 4; x++) acc2[m][n][x] = 0.f;

#pragma unroll 1
        for (int kc = 0; kc < 4; kc++) {
            if (kc < 3) { issue_g2(sb, (kc + 1) & 1, t, qb, kc + 1); cp_commit(); }
            if (kc < 3) cp_wait1(); else cp_wait0();
            __syncthreads();
            const uint32_t bA2 = sb + (kc & 1) * G2B;
            const uint32_t pB = sb + PBASE + kc * 16384;
#pragma unroll
            for (int s = 0; s < 4; s++) {
                uint32_t ah[2][4];
#pragma unroll
                for (int mt = 0; mt < 2; mt++) {
                    const int ar = 32 * wc + 16 * mt + a_row_off;
                    const uint32_t sw = (uint32_t)((ar & 7) << 4);
                    ldm_x4(ah[mt][0], ah[mt][1], ah[mt][2], ah[mt][3],
                           bA2 + ar * 128 + (((uint32_t)(s * 32 + a_col_off)) ^ sw));
                }
#pragma unroll
                for (int np = 0; np < 4; np++) {
                    const int br = 64 * wj2 + np * 16 + b_row_off;
                    const uint32_t sw = (uint32_t)((br & 7) << 4);
                    uint32_t bh[4];
                    ldm_x4(bh[0], bh[1], bh[2], bh[3],
                           pB + br * 128 + (((uint32_t)(s * 32 + b_col_off)) ^ sw));
#pragma unroll
                    for (int mt = 0; mt < 2; mt++) {
                        mma16816h(acc2[mt][2 * np],     ah[mt], bh[0], bh[1]);
                        mma16816h(acc2[mt][2 * np + 1], ah[mt], bh[2], bh[3]);
                    }
                }
            }
            __syncthreads();
        }

        // prefetch next q's GEMM1 chunk 0 (lands during epilogue)
        if (q < P_ - 1) { issue_g1(sb, 0, t, qb + B_, pb, j0, 0); cp_commit(); }

        // ===================== epilogue: RMW accumulate ======================
        {
            float* ob = out + (size_t)pb * 65536 + j0 + 64 * wj2;
#pragma unroll
            for (int mt = 0; mt < 2; mt++) {
#pragma unroll
                for (int h = 0; h < 2; h++) {
                    const int c = 32 * wc + 16 * mt + 8 * h + (lane >> 2);
                    float* rowp = ob + (size_t)c * 256;
#pragma unroll
                    for (int nt = 0; nt < 8; nt++) {
                        float v0 = acc2[mt][nt][2 * h];
                        float v1 = acc2[mt][nt][2 * h + 1];
                        float2* pp = (float2*)(rowp + nt * 8 + (lane & 3) * 2);
                        if (q == 0) {
                            *pp = make_float2(v0, v1);
                        } else {
                            float2 o = *pp;
                            o.x += v0; o.y += v1;
                            if (q == P_ - 1) { o.x *= invp; o.y *= invp; }
                            *pp = o;
                        }
                    }
                }
            }
        }
    }
}

// ---------------------------------------------------------------------------
extern "C" void kernel_launch(void* const* d_in, const int* in_sizes, int n_in,
                              void* d_out, int out_size) {
    const float* temp = (const float*)d_in[0];
    const float* We   = (const float*)d_in[1];
    const float* Wg   = (const float*)d_in[2];
    const void*  pn   = (n_in > 3) ? d_in[3] : nullptr;
    float* out = (float*)d_out;

    const int n4 = (PB_ * C_ * N_) / 4;

    corr_kernel<<<dim3(16, 64), 256>>>(temp, We);
    split_corr<<<n4 / 256, 256>>>();
    cvt_tf_f16<<<n4 / 256, 256>>>(temp);
    transpose_split<<<dim3(8, 8, 64), 256>>>(temp);
    wtf_kernel<<<64, 256>>>(temp, Wg);

    cudaFuncSetAttribute(fused_mma, cudaFuncAttributeMaxDynamicSharedMemorySize, SMEM_TOTAL);
    fused_mma<<<128, NT, SMEM_TOTAL>>>(pn, out);
}

// round 14
// speedup vs baseline: 1.3012x; 1.0329x over previous
#include <cuda_runtime.h>
#include <cuda_bf16.h>
#include <cuda_fp16.h>
#include <cstdint>

#define P_ 16
#define B_ 4
#define C_ 256
#define N_ 256
#define PB_ 64

typedef __nv_bfloat16 bf16;

// ---------------- gmem scratch ----------------
__device__ __align__(16) bf16  g_corr_h[(size_t)PB_ * N_ * C_];  // corr split [pb][j][d]
__device__ __align__(16) bf16  g_corr_l[(size_t)PB_ * N_ * C_];
__device__ __align__(16) unsigned short g_tf_f16[(size_t)PB_ * C_ * N_];  // temp fp16 [pb][c][i]
__device__ __align__(16) bf16  g_tfT_h[(size_t)PB_ * N_ * C_];   // temp^T split [pb][i][c]
__device__ __align__(16) bf16  g_tfT_l[(size_t)PB_ * N_ * C_];
__device__ __align__(16) bf16  g_We_h[(size_t)C_ * C_];          // We split [d][c]
__device__ __align__(16) bf16  g_We_l[(size_t)C_ * C_];
__device__ __align__(16) float g_wtf[(size_t)PB_ * N_];

// ---------------- helpers ----------------
__device__ __forceinline__ uint32_t smem_u32(const void* p) {
    uint32_t a;
    asm("{ .reg .u64 t; cvta.to.shared.u64 t, %1; cvt.u32.u64 %0, t; }" : "=r"(a) : "l"(p));
    return a;
}
__device__ __forceinline__ void ldm_x4(uint32_t& r0, uint32_t& r1, uint32_t& r2,
                                       uint32_t& r3, uint32_t a) {
    asm volatile("ldmatrix.sync.aligned.m8n8.x4.shared.b16 {%0,%1,%2,%3}, [%4];"
                 : "=r"(r0), "=r"(r1), "=r"(r2), "=r"(r3) : "r"(a));
}
__device__ __forceinline__ void mma16816(float* c, const uint32_t* a,
                                         uint32_t b0, uint32_t b1) {
    asm volatile("mma.sync.aligned.m16n8k16.row.col.f32.bf16.bf16.f32 "
                 "{%0,%1,%2,%3}, {%4,%5,%6,%7}, {%8,%9}, {%0,%1,%2,%3};"
                 : "+f"(c[0]), "+f"(c[1]), "+f"(c[2]), "+f"(c[3])
                 : "r"(a[0]), "r"(a[1]), "r"(a[2]), "r"(a[3]), "r"(b0), "r"(b1));
}
__device__ __forceinline__ void mma16816h(float* c, const uint32_t* a,
                                          uint32_t b0, uint32_t b1) {
    asm volatile("mma.sync.aligned.m16n8k16.row.col.f32.f16.f16.f32 "
                 "{%0,%1,%2,%3}, {%4,%5,%6,%7}, {%8,%9}, {%0,%1,%2,%3};"
                 : "+f"(c[0]), "+f"(c[1]), "+f"(c[2]), "+f"(c[3])
                 : "r"(a[0]), "r"(a[1]), "r"(a[2]), "r"(a[3]), "r"(b0), "r"(b1));
}
__device__ __forceinline__ uint32_t pack_f16(float lo, float hi) {
    uint32_t r;
    asm("cvt.rn.f16x2.f32 %0, %1, %2;" : "=r"(r) : "f"(hi), "f"(lo));
    return r;
}
__device__ __forceinline__ uint32_t pack2_bf16(bf16 lo, bf16 hi) {
    return ((uint32_t)__bfloat16_as_ushort(hi) << 16) | (uint32_t)__bfloat16_as_ushort(lo);
}
__device__ __forceinline__ void cpa16(uint32_t d, const void* s) {
    asm volatile("cp.async.cg.shared.global [%0], [%1], 16;" :: "r"(d), "l"(s));
}
__device__ __forceinline__ void cp_commit() {
    asm volatile("cp.async.commit_group;" ::: "memory");
}
__device__ __forceinline__ void cp_wait1() {
    asm volatile("cp.async.wait_group 1;" ::: "memory");
}
__device__ __forceinline__ void cp_wait0() {
    asm volatile("cp.async.wait_group 0;" ::: "memory");
}
__device__ __forceinline__ float inv_patch(const void* p) {
    if (p == nullptr) return 1.f / 16.f;
    int iv = *(const int*)p;
    if (iv >= 1 && iv <= 65536) return 1.f / (float)iv;
    float fv = __int_as_float(iv);
    if (fv >= 0.5f && fv <= 65536.f) return 1.f / fv;
    return 1.f / 16.f;
}

// ---------------------------------------------------------------------------
// Prep kernels
// ---------------------------------------------------------------------------
__device__ __forceinline__ void split4(const float4 x, uint2& uh, uint2& ul) {
    bf16 h0 = __float2bfloat16(x.x), h1 = __float2bfloat16(x.y);
    bf16 h2 = __float2bfloat16(x.z), h3 = __float2bfloat16(x.w);
    bf16 l0 = __float2bfloat16(x.x - __bfloat162float(h0));
    bf16 l1 = __float2bfloat16(x.y - __bfloat162float(h1));
    bf16 l2 = __float2bfloat16(x.z - __bfloat162float(h2));
    bf16 l3 = __float2bfloat16(x.w - __bfloat162float(h3));
    uh = make_uint2(pack2_bf16(h0, h1), pack2_bf16(h2, h3));
    ul = make_uint2(pack2_bf16(l0, l1), pack2_bf16(l2, l3));
}
__global__ void __launch_bounds__(256) split_We(const float* __restrict__ We) {
    size_t i = (size_t)blockIdx.x * 256 + threadIdx.x;
    float4 x = ((const float4*)We)[i];
    uint2 uh, ul;
    split4(x, uh, ul);
    ((uint2*)g_We_h)[i] = uh;
    ((uint2*)g_We_l)[i] = ul;
}
__global__ void __launch_bounds__(256) cvt_tf_f16(const float* __restrict__ temp) {
    size_t i = (size_t)blockIdx.x * 256 + threadIdx.x;
    float4 x = ((const float4*)temp)[i];
    ((uint2*)g_tf_f16)[i] = make_uint2(pack_f16(x.x, x.y), pack_f16(x.z, x.w));
}
__global__ void __launch_bounds__(256) transpose_split(const float* __restrict__ temp) {
    __shared__ float tile[32][33];
    const int pb = blockIdx.z;
    const int i0 = blockIdx.x * 32, c0 = blockIdx.y * 32;
    const int tx = threadIdx.x & 31, ty = threadIdx.x >> 5;
    const float* src = temp + (size_t)pb * C_ * N_;
#pragma unroll
    for (int k = 0; k < 4; k++) {
        int c = c0 + ty + k * 8;
        tile[ty + k * 8][tx] = src[(size_t)c * N_ + i0 + tx];
    }
    __syncthreads();
#pragma unroll
    for (int k = 0; k < 4; k++) {
        int i = i0 + ty + k * 8;
        float x = tile[tx][ty + k * 8];
        size_t o = (size_t)pb * N_ * C_ + (size_t)i * C_ + c0 + tx;
        bf16 hh = __float2bfloat16(x);
        g_tfT_h[o] = hh;
        g_tfT_l[o] = __float2bfloat16(x - __bfloat162float(hh));
    }
}
__global__ void __launch_bounds__(256) wtf_kernel(const float* __restrict__ temp,
                                                  const float* __restrict__ Wg) {
    __shared__ float sWg[256];
    const int pb = blockIdx.x, i = threadIdx.x;
    sWg[i] = Wg[i];
    __syncthreads();
    const float* src = temp + (size_t)pb * C_ * N_;
    float s = 0.f;
#pragma unroll 8
    for (int c = 0; c < 256; c++) s += src[(size_t)c * N_ + i] * sWg[c];
    g_wtf[(size_t)pb * N_ + i] = s;
}

// ---------------------------------------------------------------------------
// corr via mma: corr[pb][i][d] = sum_c tfT[pb][i][c] * We[d][c]  (bf16 3-split)
// grid (2, 64): x = i-half, y = pb. 512 threads. Output 128 x 256 per CTA.
// ---------------------------------------------------------------------------
#define STGC 49152

__device__ __forceinline__ void issue_cm(uint32_t sb, int buf, int t,
                                         int pb, int ih, int kc) {
    {   // B: We 256 rows x [64B hi | 64B lo]
        const int row = t >> 1, half = t & 1;
        const bf16* src = (half ? g_We_l : g_We_h) + (size_t)row * 256 + (size_t)kc * 32;
        const uint32_t dst = sb + buf * STGC + row * 128;
        const uint32_t sw = (uint32_t)((row & 7) << 4);
#pragma unroll
        for (int v = 0; v < 4; v++)
            cpa16(dst + (((uint32_t)(half * 64 + v * 16)) ^ sw), src + v * 8);
    }
    {   // A: tfT rows ih*128..
#pragma unroll
        for (int u = 0; u < 2; u++) {
            const int idx = t * 2 + u;
            const int row = idx >> 3, v = idx & 7;
            const bf16* srcp = (v < 4 ? g_tfT_h : g_tfT_l) +
                               ((size_t)pb * 65536 + (size_t)(ih * 128 + row) * 256 +
                                (size_t)kc * 32 + (size_t)(v & 3) * 8);
            const uint32_t d = sb + buf * STGC + 32768 + row * 128 +
                               (((uint32_t)(v * 16)) ^ ((uint32_t)((row & 7) << 4)));
            cpa16(d, srcp);
        }
    }
}

__global__ void __launch_bounds__(512, 1)
corr_mma() {
    extern __shared__ char smd[];
    const uint32_t sb = smem_u32(smd);
    const int t = threadIdx.x;
    const int w = t >> 5, lane = t & 31;
    const int ih = blockIdx.x;
    const int pb = blockIdx.y;

    const int wj = w >> 1, wi = w & 1;   // 8 i-warps(16) x 2 d-warps(128)
    const int a_row_off = ((lane >> 3) & 1) * 8 + (lane & 7);
    const int a_col_off = ((lane >> 4) & 1) * 16;
    const int b_row_off = ((lane >> 4) & 1) * 8 + (lane & 7);
    const int b_col_off = ((lane >> 3) & 1) * 16;

    float acc[16][4];
#pragma unroll
    for (int n = 0; n < 16; n++)
#pragma unroll
        for (int x = 0; x < 4; x++) acc[n][x] = 0.f;

    issue_cm(sb, 0, t, pb, ih, 0);
    cp_commit();

#pragma unroll 1
    for (int kc = 0; kc < 8; kc++) {
        if (kc < 7) { issue_cm(sb, (kc + 1) & 1, t, pb, ih, kc + 1); cp_commit(); }
        if (kc < 7) cp_wait1(); else cp_wait0();
        __syncthreads();
        const uint32_t bB = sb + (kc & 1) * STGC;
        const uint32_t bA = bB + 32768;
#pragma unroll
        for (int s = 0; s < 2; s++) {
            uint32_t ah[4], al[4];
            {
                const int ar = 16 * wj + a_row_off;
                const uint32_t sw = (uint32_t)((ar & 7) << 4);
                const uint32_t ad = bA + ar * 128;
                ldm_x4(ah[0], ah[1], ah[2], ah[3],
                       ad + (((uint32_t)(s * 32 + a_col_off)) ^ sw));
                ldm_x4(al[0], al[1], al[2], al[3],
                       ad + (((uint32_t)(64 + s * 32 + a_col_off)) ^ sw));
            }
#pragma unroll
            for (int np = 0; np < 8; np++) {
                const int br = 128 * wi + np * 16 + b_row_off;
                const uint32_t sw = (uint32_t)((br & 7) << 4);
                const uint32_t bd = bB + br * 128;
                uint32_t bh[4], bl[4];
                ldm_x4(bh[0], bh[1], bh[2], bh[3],
                       bd + (((uint32_t)(s * 32 + b_col_off)) ^ sw));
                ldm_x4(bl[0], bl[1], bl[2], bl[3],
                       bd + (((uint32_t)(64 + s * 32 + b_col_off)) ^ sw));
                float* e = acc[2 * np];
                float* o = acc[2 * np + 1];
                mma16816(e, ah, bh[0], bh[1]);
                mma16816(o, ah, bh[2], bh[3]);
                mma16816(e, ah, bl[0], bl[1]);
                mma16816(o, ah, bl[2], bl[3]);
                mma16816(e, al, bh[0], bh[1]);
                mma16816(o, al, bh[2], bh[3]);
            }
        }
        __syncthreads();
    }

    // epilogue: split fp32 acc -> bf16 hi/lo, store
    const int r1 = 16 * wj + (lane >> 2);
    const int r2 = r1 + 8;
#pragma unroll
    for (int nt = 0; nt < 16; nt++) {
        const int d = 128 * wi + nt * 8 + (lane & 3) * 2;
#pragma unroll
        for (int rr = 0; rr < 2; rr++) {
            const int i = ih * 128 + (rr ? r2 : r1);
            float x0 = acc[nt][rr * 2 + 0], x1 = acc[nt][rr * 2 + 1];
            bf16 h0 = __float2bfloat16(x0), h1 = __float2bfloat16(x1);
            bf16 l0 = __float2bfloat16(x0 - __bfloat162float(h0));
            bf16 l1 = __float2bfloat16(x1 - __bfloat162float(h1));
            const size_t o = (size_t)pb * 65536 + (size_t)i * 256 + d;
            *(uint32_t*)(g_corr_h + o) = pack2_bf16(h0, h1);
            *(uint32_t*)(g_corr_l + o) = pack2_bf16(l0, l1);
        }
    }
}

// ---------------------------------------------------------------------------
// Fused kernel. 128 CTAs = 64 pb x 2 j-tiles(128). 512 threads.
// SMEM: [0,64K) two 32K stage bufs
//       [64K,192K) P region: fp32 raw-exp chunks (4 x 32K) during GEMM1;
//                  after rescale, fp16 P' chunks (4 x 16K) at [64K,128K)
//       [192K+] sWtf 1K | sSum 1K | sG 1K | sScale 512B
// GEMM1 two i-passes (acc1 32 regs); raw exp stored fp32 (NO overflow);
// rescale converts to scaled fp16; acc2 persists across q; single epilogue.
// ---------------------------------------------------------------------------
#define STG1B 32768
#define PF    65536
#define SWTF  196608
#define SSUM  197632
#define SGG   198656
#define SSCL  199680
#define SMEM_TOTAL 200192
#define NT 512

__device__ __forceinline__ void issue_g1(uint32_t sb, int buf, int t,
                                         int qb, int pb, int j0, int pass, int kc) {
    {   // B: tfT rows [pass*128, +128), 32B per thread
        const int row = t >> 2, qtr = t & 3;
        const bf16* src = (qtr < 2 ? g_tfT_h : g_tfT_l) +
                          ((size_t)qb * 65536 + (size_t)(pass * 128 + row) * 256 +
                           (size_t)kc * 32 + (size_t)(qtr & 1) * 16);
        const uint32_t dst = sb + buf * STG1B + row * 128;
        const uint32_t sw = (uint32_t)((row & 7) << 4);
        const uint32_t base = (uint32_t)((qtr >= 2 ? 64 : 0) + (qtr & 1) * 32);
#pragma unroll
        for (int v = 0; v < 2; v++)
            cpa16(dst + ((base + v * 16) ^ sw), src + v * 8);
    }
    {   // A: corr rows j0..j0+127
#pragma unroll
        for (int u = 0; u < 2; u++) {
            const int idx = t * 2 + u;
            const int row = idx >> 3, v = idx & 7;
            const bf16* srcp = (v < 4 ? g_corr_h : g_corr_l) +
                               ((size_t)pb * 65536 + (size_t)(j0 + row) * 256 +
                                (size_t)kc * 32 + (size_t)(v & 3) * 8);
            const uint32_t d = sb + buf * STG1B + 16384 + row * 128 +
                               (((uint32_t)(v * 16)) ^ ((uint32_t)((row & 7) << 4)));
            cpa16(d, srcp);
        }
    }
}

__device__ __forceinline__ void issue_g2(uint32_t sb, int buf, int t, int qb, int kc) {
    const int row = t >> 1, half = t & 1;
    const unsigned short* src = g_tf_f16 + (size_t)qb * 65536 + (size_t)row * 256 +
                                (size_t)kc * 64 + (size_t)half * 32;
    const uint32_t dst = sb + buf * STG1B + row * 128;
    const uint32_t sw = (uint32_t)((row & 7) << 4);
#pragma unroll
    for (int v = 0; v < 4; v++)
        cpa16(dst + (((uint32_t)(half * 64 + v * 16)) ^ sw), src + v * 8);
}

__global__ void __launch_bounds__(NT, 1)
fused_mma(const void* __restrict__ pnp, float* __restrict__ out) {
    extern __shared__ char smd[];
    const uint32_t sb = smem_u32(smd);
    float* sWtf = (float*)(smd + SWTF);
    float* sSum = (float*)(smd + SSUM);   // [2][128]
    float* sG   = (float*)(smd + SGG);    // [2][128]
    float* sScl = (float*)(smd + SSCL);   // [128]

    const int t = threadIdx.x;
    const int w = t >> 5, lane = t & 31;
    const int jt = blockIdx.x & 1;
    const int pb = blockIdx.x >> 1;
    const int b = pb & 3;
    const int j0 = jt * 128;

    const int wj = w >> 1, wi = w & 1;      // GEMM1: 8 j-warps(16j) x 2 i-warps(64i/pass)
    const int wc = w >> 1, wj2 = w & 1;     // GEMM2: 8 c-warps(32c) x 2 j-warps(64j)
    const float invp = inv_patch(pnp);

    const int a_row_off = ((lane >> 3) & 1) * 8 + (lane & 7);
    const int a_col_off = ((lane >> 4) & 1) * 16;
    const int b_row_off = ((lane >> 4) & 1) * 8 + (lane & 7);
    const int b_col_off = ((lane >> 3) & 1) * 16;

    // persistent output accumulator (gated att summed over q)
    float acc2[2][8][4];
#pragma unroll
    for (int m = 0; m < 2; m++)
#pragma unroll
        for (int n = 0; n < 8; n++)
#pragma unroll
            for (int x = 0; x < 4; x++) acc2[m][n][x] = 0.f;

    issue_g1(sb, 0, t, 0 * B_ + b, pb, j0, 0, 0);
    cp_commit();

#pragma unroll 1
    for (int q = 0; q < P_; q++) {
        const int qb = q * B_ + b;
        if (t < 256) sWtf[t] = g_wtf[(size_t)qb * N_ + t];

        float srun1 = 0.f, grun1 = 0.f, srun2 = 0.f, grun2 = 0.f;

        // ===== GEMM1 in two i-passes: 128j x 128i per pass, bf16 3-term ======
#pragma unroll 1
        for (int pass = 0; pass < 2; pass++) {
            float acc1[8][4];
#pragma unroll
            for (int n = 0; n < 8; n++)
#pragma unroll
                for (int x = 0; x < 4; x++) acc1[n][x] = 0.f;

#pragma unroll 1
            for (int kc = 0; kc < 8; kc++) {
                const int step = pass * 8 + kc;
                if (step < 15) {
                    issue_g1(sb, (step + 1) & 1, t, qb, pb, j0,
                             (step + 1) >> 3, (step + 1) & 7);
                    cp_commit();
                    cp_wait1();
                } else {
                    cp_wait0();
                }
                __syncthreads();
                const uint32_t bB = sb + (step & 1) * STG1B;
                const uint32_t bA = bB + 16384;
#pragma unroll
                for (int s = 0; s < 2; s++) {
                    uint32_t ah[4], al[4];
                    {
                        const int ar = 16 * wj + a_row_off;
                        const uint32_t sw = (uint32_t)((ar & 7) << 4);
                        const uint32_t ad = bA + ar * 128;
                        ldm_x4(ah[0], ah[1], ah[2], ah[3],
                               ad + (((uint32_t)(s * 32 + a_col_off)) ^ sw));
                        ldm_x4(al[0], al[1], al[2], al[3],
                               ad + (((uint32_t)(64 + s * 32 + a_col_off)) ^ sw));
                    }
#pragma unroll
                    for (int np = 0; np < 4; np++) {
                        const int br = 64 * wi + np * 16 + b_row_off;
                        const uint32_t sw = (uint32_t)((br & 7) << 4);
                        const uint32_t bd = bB + br * 128;
                        uint32_t bh[4], bl[4];
                        ldm_x4(bh[0], bh[1], bh[2], bh[3],
                               bd + (((uint32_t)(s * 32 + b_col_off)) ^ sw));
                        ldm_x4(bl[0], bl[1], bl[2], bl[3],
                               bd + (((uint32_t)(64 + s * 32 + b_col_off)) ^ sw));
                        float* e = acc1[2 * np];
                        float* o = acc1[2 * np + 1];
                        mma16816(e, ah, bh[0], bh[1]);
                        mma16816(o, ah, bh[2], bh[3]);
                        mma16816(e, ah, bl[0], bl[1]);
                        mma16816(o, ah, bl[2], bl[3]);
                        mma16816(e, al, bh[0], bh[1]);
                        mma16816(o, al, bh[2], bh[3]);
                    }
                }
                __syncthreads();
            }

            // exp + partial sums + RAW exp written to fp32 staging (no overflow)
            {
                const int r1 = 16 * wj + (lane >> 2);
                const int r2 = r1 + 8;
                const int ch = pass * 2 + wi;   // i-chunk 0..3 (64 i each)
                char* base32 = smd + PF + ch * 32768;
#pragma unroll
                for (int nt = 0; nt < 8; nt++) {
                    const int col = pass * 128 + 64 * wi + nt * 8 + (lane & 3) * 2;
                    float2 wv = *(float2*)&sWtf[col];
                    float e0 = __expf(acc1[nt][0] - 40.f);
                    float e1 = __expf(acc1[nt][1] - 40.f);
                    float e2 = __expf(acc1[nt][2] - 40.f);
                    float e3 = __expf(acc1[nt][3] - 40.f);
                    srun1 += e0 + e1; grun1 += e0 * wv.x + e1 * wv.y;
                    srun2 += e2 + e3; grun2 += e2 * wv.x + e3 * wv.y;
                    const uint32_t off32 = (uint32_t)(nt * 32 + (lane & 3) * 8);
                    *(float2*)(base32 + r1 * 256 + off32) = make_float2(e0, e1);
                    *(float2*)(base32 + r2 * 256 + off32) = make_float2(e2, e3);
                }
            }
        }

        // prefetch GEMM2 chunk 0 (lands during softmax finalize)
        issue_g2(sb, 0, t, qb, 0);
        cp_commit();

        // ===== softmax finalize: row sums -> sScl =============================
        {
#pragma unroll
            for (int o = 1; o <= 2; o <<= 1) {
                srun1 += __shfl_xor_sync(0xffffffffu, srun1, o);
                grun1 += __shfl_xor_sync(0xffffffffu, grun1, o);
                srun2 += __shfl_xor_sync(0xffffffffu, srun2, o);
                grun2 += __shfl_xor_sync(0xffffffffu, grun2, o);
            }
            const int r1 = 16 * wj + (lane >> 2);
            if ((lane & 3) == 0) {
                sSum[wi * 128 + r1] = srun1;     sG[wi * 128 + r1] = grun1;
                sSum[wi * 128 + r1 + 8] = srun2; sG[wi * 128 + r1 + 8] = grun2;
            }
            __syncthreads();
            if (wi == 0 && (lane & 3) == 0) {
#pragma unroll
                for (int h = 0; h < 2; h++) {
                    const int r = r1 + 8 * h;
                    const float tot = sSum[r] + sSum[128 + r];
                    const float gt  = sG[r] + sG[128 + r];
                    sScl[r] = (1.f / (1.f + __expf(-gt / tot))) / tot;
                }
            }
            __syncthreads();
        }

        // ===== rescale sweep: fp32 raw exp -> scaled fp16 P' chunks ==========
        {
            const int prow = t >> 2;                 // P row 0..127
            const float scv = sScl[prow];
            const uint32_t sw = (uint32_t)((prow & 7) << 4);
            const uint32_t cb2 = (uint32_t)((t & 3) * 32);   // first pair byte in fp16 row
#pragma unroll 1
            for (int ch = 0; ch < 4; ch++) {
                const float4* src = (const float4*)(smd + PF + ch * 32768 + t * 64);
                float4 a0 = src[0], a1 = src[1], a2 = src[2], a3 = src[3];
                if (ch == 0) __syncthreads();   // fp16 chunk0 aliases fp32 chunk0
                char* row = smd + PF + ch * 16384 + prow * 128;
                *(uint32_t*)(row + ((cb2 + 0)  ^ sw)) = pack_f16(a0.x * scv, a0.y * scv);
                *(uint32_t*)(row + ((cb2 + 4)  ^ sw)) = pack_f16(a0.z * scv, a0.w * scv);
                *(uint32_t*)(row + ((cb2 + 8)  ^ sw)) = pack_f16(a1.x * scv, a1.y * scv);
                *(uint32_t*)(row + ((cb2 + 12) ^ sw)) = pack_f16(a1.z * scv, a1.w * scv);
                *(uint32_t*)(row + ((cb2 + 16) ^ sw)) = pack_f16(a2.x * scv, a2.y * scv);
                *(uint32_t*)(row + ((cb2 + 20) ^ sw)) = pack_f16(a2.z * scv, a2.w * scv);
                *(uint32_t*)(row + ((cb2 + 24) ^ sw)) = pack_f16(a3.x * scv, a3.y * scv);
                *(uint32_t*)(row + ((cb2 + 28) ^ sw)) = pack_f16(a3.z * scv, a3.w * scv);
            }
        }

        // ===== GEMM2: acc2 += tf_f16 . P'^T  (accumulates across q) ==========
#pragma unroll 1
        for (int kc = 0; kc < 4; kc++) {
            if (kc < 3) { issue_g2(sb, (kc + 1) & 1, t, qb, kc + 1); cp_commit(); }
            if (kc < 3) cp_wait1(); else cp_wait0();
            __syncthreads();
            const uint32_t bA2 = sb + (kc & 1) * STG1B;
            const uint32_t pB = sb + PF + kc * 16384;
#pragma unroll
            for (int s = 0; s < 4; s++) {
                uint32_t ah[2][4];
#pragma unroll
                for (int mt = 0; mt < 2; mt++) {
                    const int ar = 32 * wc + 16 * mt + a_row_off;
                    const uint32_t sw = (uint32_t)((ar & 7) << 4);
                    ldm_x4(ah[mt][0], ah[mt][1], ah[mt][2], ah[mt][3],
                           bA2 + ar * 128 + (((uint32_t)(s * 32 + a_col_off)) ^ sw));
                }
#pragma unroll
                for (int np = 0; np < 4; np++) {
                    const int br = 64 * wj2 + np * 16 + b_row_off;
                    const uint32_t sw = (uint32_t)((br & 7) << 4);
                    uint32_t bh[4];
                    ldm_x4(bh[0], bh[1], bh[2], bh[3],
                           pB + br * 128 + (((uint32_t)(s * 32 + b_col_off)) ^ sw));
#pragma unroll
                    for (int mt = 0; mt < 2; mt++) {
                        mma16816h(acc2[mt][2 * np],     ah[mt], bh[0], bh[1]);
                        mma16816h(acc2[mt][2 * np + 1], ah[mt], bh[2], bh[3]);
                    }
                }
            }
            __syncthreads();
        }

        // prefetch next q's GEMM1 step 0
        if (q < P_ - 1) { issue_g1(sb, 0, t, qb + B_, pb, j0, 0, 0); cp_commit(); }
    }

    // ===================== final epilogue: pure store ========================
    {
        float* ob = out + (size_t)pb * 65536 + j0 + 64 * wj2;
#pragma unroll
        for (int mt = 0; mt < 2; mt++) {
#pragma unroll
            for (int h = 0; h < 2; h++) {
                const int c = 32 * wc + 16 * mt + 8 * h + (lane >> 2);
                float* rowp = ob + (size_t)c * 256;
#pragma unroll
                for (int nt = 0; nt < 8; nt++) {
                    float2 o;
                    o.x = acc2[mt][nt][2 * h] * invp;
                    o.y = acc2[mt][nt][2 * h + 1] * invp;
                    *(float2*)(rowp + nt * 8 + (lane & 3) * 2) = o;
                }
            }
        }
    }
}

// ---------------------------------------------------------------------------
extern "C" void kernel_launch(void* const* d_in, const int* in_sizes, int n_in,
                              void* d_out, int out_size) {
    const float* temp = (const float*)d_in[0];
    const float* We   = (const float*)d_in[1];
    const float* Wg   = (const float*)d_in[2];
    const void*  pn   = (n_in > 3) ? d_in[3] : nullptr;
    float* out = (float*)d_out;

    const int n4 = (PB_ * C_ * N_) / 4;

    transpose_split<<<dim3(8, 8, 64), 256>>>(temp);
    split_We<<<64, 256>>>(We);
    cvt_tf_f16<<<n4 / 256, 256>>>(temp);
    wtf_kernel<<<64, 256>>>(temp, Wg);

    cudaFuncSetAttribute(corr_mma, cudaFuncAttributeMaxDynamicSharedMemorySize, 2 * STGC);
    corr_mma<<<dim3(2, 64), 512, 2 * STGC>>>();

    cudaFuncSetAttribute(fused_mma, cudaFuncAttributeMaxDynamicSharedMemorySize, SMEM_TOTAL);
    fused_mma<<<128, NT, SMEM_TOTAL>>>(pn, out);
}

// round 15
// speedup vs baseline: 1.3242x; 1.0177x over previous
#include <cuda_runtime.h>
#include <cuda_bf16.h>
#include <cuda_fp16.h>
#include <cstdint>

#define P_ 16
#define B_ 4
#define C_ 256
#define N_ 256
#define PB_ 64

typedef __nv_bfloat16 bf16;

// ---------------- gmem scratch ----------------
__device__ __align__(16) bf16  g_corr_h[(size_t)PB_ * N_ * C_];  // corr split [pb][j][d]
__device__ __align__(16) bf16  g_corr_l[(size_t)PB_ * N_ * C_];
__device__ __align__(16) unsigned short g_tf_f16[(size_t)PB_ * C_ * N_];  // temp fp16 [pb][c][i]
__device__ __align__(16) bf16  g_tfT_h[(size_t)PB_ * N_ * C_];   // temp^T split [pb][i][c]
__device__ __align__(16) bf16  g_tfT_l[(size_t)PB_ * N_ * C_];
__device__ __align__(16) bf16  g_We_h[(size_t)C_ * C_];          // We split [d][c]
__device__ __align__(16) bf16  g_We_l[(size_t)C_ * C_];
__device__ __align__(16) float g_wtf[(size_t)PB_ * N_];

// ---------------- helpers ----------------
__device__ __forceinline__ uint32_t smem_u32(const void* p) {
    uint32_t a;
    asm("{ .reg .u64 t; cvta.to.shared.u64 t, %1; cvt.u32.u64 %0, t; }" : "=r"(a) : "l"(p));
    return a;
}
__device__ __forceinline__ void ldm_x4(uint32_t& r0, uint32_t& r1, uint32_t& r2,
                                       uint32_t& r3, uint32_t a) {
    asm volatile("ldmatrix.sync.aligned.m8n8.x4.shared.b16 {%0,%1,%2,%3}, [%4];"
                 : "=r"(r0), "=r"(r1), "=r"(r2), "=r"(r3) : "r"(a));
}
__device__ __forceinline__ void mma16816(float* c, const uint32_t* a,
                                         uint32_t b0, uint32_t b1) {
    asm volatile("mma.sync.aligned.m16n8k16.row.col.f32.bf16.bf16.f32 "
                 "{%0,%1,%2,%3}, {%4,%5,%6,%7}, {%8,%9}, {%0,%1,%2,%3};"
                 : "+f"(c[0]), "+f"(c[1]), "+f"(c[2]), "+f"(c[3])
                 : "r"(a[0]), "r"(a[1]), "r"(a[2]), "r"(a[3]), "r"(b0), "r"(b1));
}
__device__ __forceinline__ void mma16816h(float* c, const uint32_t* a,
                                          uint32_t b0, uint32_t b1) {
    asm volatile("mma.sync.aligned.m16n8k16.row.col.f32.f16.f16.f32 "
                 "{%0,%1,%2,%3}, {%4,%5,%6,%7}, {%8,%9}, {%0,%1,%2,%3};"
                 : "+f"(c[0]), "+f"(c[1]), "+f"(c[2]), "+f"(c[3])
                 : "r"(a[0]), "r"(a[1]), "r"(a[2]), "r"(a[3]), "r"(b0), "r"(b1));
}
__device__ __forceinline__ uint32_t pack_f16(float lo, float hi) {
    uint32_t r;
    asm("cvt.rn.f16x2.f32 %0, %1, %2;" : "=r"(r) : "f"(hi), "f"(lo));
    return r;
}
__device__ __forceinline__ uint32_t pack2_bf16(bf16 lo, bf16 hi) {
    return ((uint32_t)__bfloat16_as_ushort(hi) << 16) | (uint32_t)__bfloat16_as_ushort(lo);
}
__device__ __forceinline__ void cpa16(uint32_t d, const void* s) {
    asm volatile("cp.async.cg.shared.global [%0], [%1], 16;" :: "r"(d), "l"(s));
}
__device__ __forceinline__ void cp_commit() {
    asm volatile("cp.async.commit_group;" ::: "memory");
}
__device__ __forceinline__ void cp_wait1() {
    asm volatile("cp.async.wait_group 1;" ::: "memory");
}
__device__ __forceinline__ void cp_wait0() {
    asm volatile("cp.async.wait_group 0;" ::: "memory");
}
__device__ __forceinline__ float inv_patch(const void* p) {
    if (p == nullptr) return 1.f / 16.f;
    int iv = *(const int*)p;
    if (iv >= 1 && iv <= 65536) return 1.f / (float)iv;
    float fv = __int_as_float(iv);
    if (fv >= 0.5f && fv <= 65536.f) return 1.f / fv;
    return 1.f / 16.f;
}

// ---------------------------------------------------------------------------
// Prep kernels
// ---------------------------------------------------------------------------
__device__ __forceinline__ void split4(const float4 x, uint2& uh, uint2& ul) {
    bf16 h0 = __float2bfloat16(x.x), h1 = __float2bfloat16(x.y);
    bf16 h2 = __float2bfloat16(x.z), h3 = __float2bfloat16(x.w);
    bf16 l0 = __float2bfloat16(x.x - __bfloat162float(h0));
    bf16 l1 = __float2bfloat16(x.y - __bfloat162float(h1));
    bf16 l2 = __float2bfloat16(x.z - __bfloat162float(h2));
    bf16 l3 = __float2bfloat16(x.w - __bfloat162float(h3));
    uh = make_uint2(pack2_bf16(h0, h1), pack2_bf16(h2, h3));
    ul = make_uint2(pack2_bf16(l0, l1), pack2_bf16(l2, l3));
}
__global__ void __launch_bounds__(256) split_We(const float* __restrict__ We) {
    size_t i = (size_t)blockIdx.x * 256 + threadIdx.x;
    float4 x = ((const float4*)We)[i];
    uint2 uh, ul;
    split4(x, uh, ul);
    ((uint2*)g_We_h)[i] = uh;
    ((uint2*)g_We_l)[i] = ul;
}

// transpose + bf16 split of temp^T + fp16 copy of temp (single read pass)
__global__ void __launch_bounds__(256) transpose_split(const float* __restrict__ temp) {
    __shared__ float tile[32][33];
    const int pb = blockIdx.z;
    const int i0 = blockIdx.x * 32, c0 = blockIdx.y * 32;
    const int tx = threadIdx.x & 31, ty = threadIdx.x >> 5;
    const float* src = temp + (size_t)pb * C_ * N_;
#pragma unroll
    for (int k = 0; k < 4; k++) {
        int c = c0 + ty + k * 8;
        float x = src[(size_t)c * N_ + i0 + tx];
        tile[ty + k * 8][tx] = x;
        g_tf_f16[(size_t)pb * 65536 + (size_t)c * N_ + i0 + tx] =
            __half_as_ushort(__float2half(x));
    }
    __syncthreads();
#pragma unroll
    for (int k = 0; k < 4; k++) {
        int i = i0 + ty + k * 8;
        float x = tile[tx][ty + k * 8];
        size_t o = (size_t)pb * N_ * C_ + (size_t)i * C_ + c0 + tx;
        bf16 hh = __float2bfloat16(x);
        g_tfT_h[o] = hh;
        g_tfT_l[o] = __float2bfloat16(x - __bfloat162float(hh));
    }
}

__global__ void __launch_bounds__(1024) zero_wtf() {
    g_wtf[blockIdx.x * 1024 + threadIdx.x] = 0.f;
}

// wtf partial: grid (64 pb, 8 c-chunks); CTA reduces 32 c-rows over 256 i.
__global__ void __launch_bounds__(256) wtf_part(const float* __restrict__ temp,
                                                const float* __restrict__ Wg) {
    __shared__ float sWg[32];
    const int pb = blockIdx.x, cc = blockIdx.y;
    const int i = threadIdx.x;
    if (i < 32) sWg[i] = Wg[cc * 32 + i];
    __syncthreads();
    const float* src = temp + (size_t)pb * C_ * N_ + (size_t)cc * 32 * N_;
    float s = 0.f;
#pragma unroll 8
    for (int c = 0; c < 32; c++) s += src[(size_t)c * N_ + i] * sWg[c];
    atomicAdd(&g_wtf[(size_t)pb * N_ + i], s);
}

// ---------------------------------------------------------------------------
// corr via mma: corr[pb][i][d] = sum_c tfT[pb][i][c] * We[d][c]  (bf16 3-split)
// grid (2, 64): x = i-half, y = pb. 512 threads. Output 128 x 256 per CTA.
// ---------------------------------------------------------------------------
#define STGC 49152

__device__ __forceinline__ void issue_cm(uint32_t sb, int buf, int t,
                                         int pb, int ih, int kc) {
    {   // B: We 256 rows x [64B hi | 64B lo]
        const int row = t >> 1, half = t & 1;
        const bf16* src = (half ? g_We_l : g_We_h) + (size_t)row * 256 + (size_t)kc * 32;
        const uint32_t dst = sb + buf * STGC + row * 128;
        const uint32_t sw = (uint32_t)((row & 7) << 4);
#pragma unroll
        for (int v = 0; v < 4; v++)
            cpa16(dst + (((uint32_t)(half * 64 + v * 16)) ^ sw), src + v * 8);
    }
    {   // A: tfT rows ih*128..
#pragma unroll
        for (int u = 0; u < 2; u++) {
            const int idx = t * 2 + u;
            const int row = idx >> 3, v = idx & 7;
            const bf16* srcp = (v < 4 ? g_tfT_h : g_tfT_l) +
                               ((size_t)pb * 65536 + (size_t)(ih * 128 + row) * 256 +
                                (size_t)kc * 32 + (size_t)(v & 3) * 8);
            const uint32_t d = sb + buf * STGC + 32768 + row * 128 +
                               (((uint32_t)(v * 16)) ^ ((uint32_t)((row & 7) << 4)));
            cpa16(d, srcp);
        }
    }
}

__global__ void __launch_bounds__(512, 1)
corr_mma() {
    extern __shared__ char smd[];
    const uint32_t sb = smem_u32(smd);
    const int t = threadIdx.x;
    const int w = t >> 5, lane = t & 31;
    const int ih = blockIdx.x;
    const int pb = blockIdx.y;

    const int wj = w >> 1, wi = w & 1;   // 8 i-warps(16) x 2 d-warps(128)
    const int a_row_off = ((lane >> 3) & 1) * 8 + (lane & 7);
    const int a_col_off = ((lane >> 4) & 1) * 16;
    const int b_row_off = ((lane >> 4) & 1) * 8 + (lane & 7);
    const int b_col_off = ((lane >> 3) & 1) * 16;

    float acc[16][4];
#pragma unroll
    for (int n = 0; n < 16; n++)
#pragma unroll
        for (int x = 0; x < 4; x++) acc[n][x] = 0.f;

    issue_cm(sb, 0, t, pb, ih, 0);
    cp_commit();

#pragma unroll 1
    for (int kc = 0; kc < 8; kc++) {
        if (kc < 7) { issue_cm(sb, (kc + 1) & 1, t, pb, ih, kc + 1); cp_commit(); }
        if (kc < 7) cp_wait1(); else cp_wait0();
        __syncthreads();
        const uint32_t bB = sb + (kc & 1) * STGC;
        const uint32_t bA = bB + 32768;
#pragma unroll
        for (int s = 0; s < 2; s++) {
            uint32_t ah[4], al[4];
            {
                const int ar = 16 * wj + a_row_off;
                const uint32_t sw = (uint32_t)((ar & 7) << 4);
                const uint32_t ad = bA + ar * 128;
                ldm_x4(ah[0], ah[1], ah[2], ah[3],
                       ad + (((uint32_t)(s * 32 + a_col_off)) ^ sw));
                ldm_x4(al[0], al[1], al[2], al[3],
                       ad + (((uint32_t)(64 + s * 32 + a_col_off)) ^ sw));
            }
#pragma unroll
            for (int np = 0; np < 8; np++) {
                const int br = 128 * wi + np * 16 + b_row_off;
                const uint32_t sw = (uint32_t)((br & 7) << 4);
                const uint32_t bd = bB + br * 128;
                uint32_t bh[4], bl[4];
                ldm_x4(bh[0], bh[1], bh[2], bh[3],
                       bd + (((uint32_t)(s * 32 + b_col_off)) ^ sw));
                ldm_x4(bl[0], bl[1], bl[2], bl[3],
                       bd + (((uint32_t)(64 + s * 32 + b_col_off)) ^ sw));
                float* e = acc[2 * np];
                float* o = acc[2 * np + 1];
                mma16816(e, ah, bh[0], bh[1]);
                mma16816(o, ah, bh[2], bh[3]);
                mma16816(e, ah, bl[0], bl[1]);
                mma16816(o, ah, bl[2], bl[3]);
                mma16816(e, al, bh[0], bh[1]);
                mma16816(o, al, bh[2], bh[3]);
            }
        }
        __syncthreads();
    }

    // epilogue: split fp32 acc -> bf16 hi/lo, store
    const int r1 = 16 * wj + (lane >> 2);
    const int r2 = r1 + 8;
#pragma unroll
    for (int nt = 0; nt < 16; nt++) {
        const int d = 128 * wi + nt * 8 + (lane & 3) * 2;
#pragma unroll
        for (int rr = 0; rr < 2; rr++) {
            const int i = ih * 128 + (rr ? r2 : r1);
            float x0 = acc[nt][rr * 2 + 0], x1 = acc[nt][rr * 2 + 1];
            bf16 h0 = __float2bfloat16(x0), h1 = __float2bfloat16(x1);
            bf16 l0 = __float2bfloat16(x0 - __bfloat162float(h0));
            bf16 l1 = __float2bfloat16(x1 - __bfloat162float(h1));
            const size_t o = (size_t)pb * 65536 + (size_t)i * 256 + d;
            *(uint32_t*)(g_corr_h + o) = pack2_bf16(h0, h1);
            *(uint32_t*)(g_corr_l + o) = pack2_bf16(l0, l1);
        }
    }
}

// ---------------------------------------------------------------------------
// Fused kernel (identical to R14, verified). 128 CTAs, 512 threads.
// ---------------------------------------------------------------------------
#define STG1B 32768
#define PF    65536
#define SWTF  196608
#define SSUM  197632
#define SGG   198656
#define SSCL  199680
#define SMEM_TOTAL 200192
#define NT 512

__device__ __forceinline__ void issue_g1(uint32_t sb, int buf, int t,
                                         int qb, int pb, int j0, int pass, int kc) {
    {   // B: tfT rows [pass*128, +128), 32B per thread
        const int row = t >> 2, qtr = t & 3;
        const bf16* src = (qtr < 2 ? g_tfT_h : g_tfT_l) +
                          ((size_t)qb * 65536 + (size_t)(pass * 128 + row) * 256 +
                           (size_t)kc * 32 + (size_t)(qtr & 1) * 16);
        const uint32_t dst = sb + buf * STG1B + row * 128;
        const uint32_t sw = (uint32_t)((row & 7) << 4);
        const uint32_t base = (uint32_t)((qtr >= 2 ? 64 : 0) + (qtr & 1) * 32);
#pragma unroll
        for (int v = 0; v < 2; v++)
            cpa16(dst + ((base + v * 16) ^ sw), src + v * 8);
    }
    {   // A: corr rows j0..j0+127
#pragma unroll
        for (int u = 0; u < 2; u++) {
            const int idx = t * 2 + u;
            const int row = idx >> 3, v = idx & 7;
            const bf16* srcp = (v < 4 ? g_corr_h : g_corr_l) +
                               ((size_t)pb * 65536 + (size_t)(j0 + row) * 256 +
                                (size_t)kc * 32 + (size_t)(v & 3) * 8);
            const uint32_t d = sb + buf * STG1B + 16384 + row * 128 +
                               (((uint32_t)(v * 16)) ^ ((uint32_t)((row & 7) << 4)));
            cpa16(d, srcp);
        }
    }
}

__device__ __forceinline__ void issue_g2(uint32_t sb, int buf, int t, int qb, int kc) {
    const int row = t >> 1, half = t & 1;
    const unsigned short* src = g_tf_f16 + (size_t)qb * 65536 + (size_t)row * 256 +
                                (size_t)kc * 64 + (size_t)half * 32;
    const uint32_t dst = sb + buf * STG1B + row * 128;
    const uint32_t sw = (uint32_t)((row & 7) << 4);
#pragma unroll
    for (int v = 0; v < 4; v++)
        cpa16(dst + (((uint32_t)(half * 64 + v * 16)) ^ sw), src + v * 8);
}

__global__ void __launch_bounds__(NT, 1)
fused_mma(const void* __restrict__ pnp, float* __restrict__ out) {
    extern __shared__ char smd[];
    const uint32_t sb = smem_u32(smd);
    float* sWtf = (float*)(smd + SWTF);
    float* sSum = (float*)(smd + SSUM);   // [2][128]
    float* sG   = (float*)(smd + SGG);    // [2][128]
    float* sScl = (float*)(smd + SSCL);   // [128]

    const int t = threadIdx.x;
    const int w = t >> 5, lane = t & 31;
    const int jt = blockIdx.x & 1;
    const int pb = blockIdx.x >> 1;
    const int b = pb & 3;
    const int j0 = jt * 128;

    const int wj = w >> 1, wi = w & 1;      // GEMM1: 8 j-warps(16j) x 2 i-warps(64i/pass)
    const int wc = w >> 1, wj2 = w & 1;     // GEMM2: 8 c-warps(32c) x 2 j-warps(64j)
    const float invp = inv_patch(pnp);

    const int a_row_off = ((lane >> 3) & 1) * 8 + (lane & 7);
    const int a_col_off = ((lane >> 4) & 1) * 16;
    const int b_row_off = ((lane >> 4) & 1) * 8 + (lane & 7);
    const int b_col_off = ((lane >> 3) & 1) * 16;

    // persistent output accumulator (gated att summed over q)
    float acc2[2][8][4];
#pragma unroll
    for (int m = 0; m < 2; m++)
#pragma unroll
        for (int n = 0; n < 8; n++)
#pragma unroll
            for (int x = 0; x < 4; x++) acc2[m][n][x] = 0.f;

    issue_g1(sb, 0, t, 0 * B_ + b, pb, j0, 0, 0);
    cp_commit();

#pragma unroll 1
    for (int q = 0; q < P_; q++) {
        const int qb = q * B_ + b;
        if (t < 256) sWtf[t] = g_wtf[(size_t)qb * N_ + t];

        float srun1 = 0.f, grun1 = 0.f, srun2 = 0.f, grun2 = 0.f;

        // ===== GEMM1 in two i-passes: 128j x 128i per pass, bf16 3-term ======
#pragma unroll 1
        for (int pass = 0; pass < 2; pass++) {
            float acc1[8][4];
#pragma unroll
            for (int n = 0; n < 8; n++)
#pragma unroll
                for (int x = 0; x < 4; x++) acc1[n][x] = 0.f;

#pragma unroll 1
            for (int kc = 0; kc < 8; kc++) {
                const int step = pass * 8 + kc;
                if (step < 15) {
                    issue_g1(sb, (step + 1) & 1, t, qb, pb, j0,
                             (step + 1) >> 3, (step + 1) & 7);
                    cp_commit();
                    cp_wait1();
                } else {
                    cp_wait0();
                }
                __syncthreads();
                const uint32_t bB = sb + (step & 1) * STG1B;
                const uint32_t bA = bB + 16384;
#pragma unroll
                for (int s = 0; s < 2; s++) {
                    uint32_t ah[4], al[4];
                    {
                        const int ar = 16 * wj + a_row_off;
                        const uint32_t sw = (uint32_t)((ar & 7) << 4);
                        const uint32_t ad = bA + ar * 128;
                        ldm_x4(ah[0], ah[1], ah[2], ah[3],
                               ad + (((uint32_t)(s * 32 + a_col_off)) ^ sw));
                        ldm_x4(al[0], al[1], al[2], al[3],
                               ad + (((uint32_t)(64 + s * 32 + a_col_off)) ^ sw));
                    }
#pragma unroll
                    for (int np = 0; np < 4; np++) {
                        const int br = 64 * wi + np * 16 + b_row_off;
                        const uint32_t sw = (uint32_t)((br & 7) << 4);
                        const uint32_t bd = bB + br * 128;
                        uint32_t bh[4], bl[4];
                        ldm_x4(bh[0], bh[1], bh[2], bh[3],
                               bd + (((uint32_t)(s * 32 + b_col_off)) ^ sw));
                        ldm_x4(bl[0], bl[1], bl[2], bl[3],
                               bd + (((uint32_t)(64 + s * 32 + b_col_off)) ^ sw));
                        float* e = acc1[2 * np];
                        float* o = acc1[2 * np + 1];
                        mma16816(e, ah, bh[0], bh[1]);
                        mma16816(o, ah, bh[2], bh[3]);
                        mma16816(e, ah, bl[0], bl[1]);
                        mma16816(o, ah, bl[2], bl[3]);
                        mma16816(e, al, bh[0], bh[1]);
                        mma16816(o, al, bh[2], bh[3]);
                    }
                }
                __syncthreads();
            }

            // exp + partial sums + RAW exp written to fp32 staging (no overflow)
            {
                const int r1 = 16 * wj + (lane >> 2);
                const int r2 = r1 + 8;
                const int ch = pass * 2 + wi;   // i-chunk 0..3 (64 i each)
                char* base32 = smd + PF + ch * 32768;
#pragma unroll
                for (int nt = 0; nt < 8; nt++) {
                    const int col = pass * 128 + 64 * wi + nt * 8 + (lane & 3) * 2;
                    float2 wv = *(float2*)&sWtf[col];
                    float e0 = __expf(acc1[nt][0] - 40.f);
                    float e1 = __expf(acc1[nt][1] - 40.f);
                    float e2 = __expf(acc1[nt][2] - 40.f);
                    float e3 = __expf(acc1[nt][3] - 40.f);
                    srun1 += e0 + e1; grun1 += e0 * wv.x + e1 * wv.y;
                    srun2 += e2 + e3; grun2 += e2 * wv.x + e3 * wv.y;
                    const uint32_t off32 = (uint32_t)(nt * 32 + (lane & 3) * 8);
                    *(float2*)(base32 + r1 * 256 + off32) = make_float2(e0, e1);
                    *(float2*)(base32 + r2 * 256 + off32) = make_float2(e2, e3);
                }
            }
        }

        // prefetch GEMM2 chunk 0 (lands during softmax finalize)
        issue_g2(sb, 0, t, qb, 0);
        cp_commit();

        // ===== softmax finalize: row sums -> sScl =============================
        {
#pragma unroll
            for (int o = 1; o <= 2; o <<= 1) {
                srun1 += __shfl_xor_sync(0xffffffffu, srun1, o);
                grun1 += __shfl_xor_sync(0xffffffffu, grun1, o);
                srun2 += __shfl_xor_sync(0xffffffffu, srun2, o);
                grun2 += __shfl_xor_sync(0xffffffffu, grun2, o);
            }
            const int r1 = 16 * wj + (lane >> 2);
            if ((lane & 3) == 0) {
                sSum[wi * 128 + r1] = srun1;     sG[wi * 128 + r1] = grun1;
                sSum[wi * 128 + r1 + 8] = srun2; sG[wi * 128 + r1 + 8] = grun2;
            }
            __syncthreads();
            if (wi == 0 && (lane & 3) == 0) {
#pragma unroll
                for (int h = 0; h < 2; h++) {
                    const int r = r1 + 8 * h;
                    const float tot = sSum[r] + sSum[128 + r];
                    const float gt  = sG[r] + sG[128 + r];
                    sScl[r] = (1.f / (1.f + __expf(-gt / tot))) / tot;
                }
            }
            __syncthreads();
        }

        // ===== rescale sweep: fp32 raw exp -> scaled fp16 P' chunks ==========
        {
            const int prow = t >> 2;                 // P row 0..127
            const float scv = sScl[prow];
            const uint32_t sw = (uint32_t)((prow & 7) << 4);
            const uint32_t cb2 = (uint32_t)((t & 3) * 32);   // first pair byte in fp16 row
#pragma unroll 1
            for (int ch = 0; ch < 4; ch++) {
                const float4* src = (const float4*)(smd + PF + ch * 32768 + t * 64);
                float4 a0 = src[0], a1 = src[1], a2 = src[2], a3 = src[3];
                if (ch == 0) __syncthreads();   // fp16 chunk0 aliases fp32 chunk0
                char* row = smd + PF + ch * 16384 + prow * 128;
                *(uint32_t*)(row + ((cb2 + 0)  ^ sw)) = pack_f16(a0.x * scv, a0.y * scv);
                *(uint32_t*)(row + ((cb2 + 4)  ^ sw)) = pack_f16(a0.z * scv, a0.w * scv);
                *(uint32_t*)(row + ((cb2 + 8)  ^ sw)) = pack_f16(a1.x * scv, a1.y * scv);
                *(uint32_t*)(row + ((cb2 + 12) ^ sw)) = pack_f16(a1.z * scv, a1.w * scv);
                *(uint32_t*)(row + ((cb2 + 16) ^ sw)) = pack_f16(a2.x * scv, a2.y * scv);
                *(uint32_t*)(row + ((cb2 + 20) ^ sw)) = pack_f16(a2.z * scv, a2.w * scv);
                *(uint32_t*)(row + ((cb2 + 24) ^ sw)) = pack_f16(a3.x * scv, a3.y * scv);
                *(uint32_t*)(row + ((cb2 + 28) ^ sw)) = pack_f16(a3.z * scv, a3.w * scv);
            }
        }

        // ===== GEMM2: acc2 += tf_f16 . P'^T  (accumulates across q) ==========
#pragma unroll 1
        for (int kc = 0; kc < 4; kc++) {
            if (kc < 3) { issue_g2(sb, (kc + 1) & 1, t, qb, kc + 1); cp_commit(); }
            if (kc < 3) cp_wait1(); else cp_wait0();
            __syncthreads();
            const uint32_t bA2 = sb + (kc & 1) * STG1B;
            const uint32_t pB = sb + PF + kc * 16384;
#pragma unroll
            for (int s = 0; s < 4; s++) {
                uint32_t ah[2][4];
#pragma unroll
                for (int mt = 0; mt < 2; mt++) {
                    const int ar = 32 * wc + 16 * mt + a_row_off;
                    const uint32_t sw = (uint32_t)((ar & 7) << 4);
                    ldm_x4(ah[mt][0], ah[mt][1], ah[mt][2], ah[mt][3],
                           bA2 + ar * 128 + (((uint32_t)(s * 32 + a_col_off)) ^ sw));
                }
#pragma unroll
                for (int np = 0; np < 4; np++) {
                    const int br = 64 * wj2 + np * 16 + b_row_off;
                    const uint32_t sw = (uint32_t)((br & 7) << 4);
                    uint32_t bh[4];
                    ldm_x4(bh[0], bh[1], bh[2], bh[3],
                           pB + br * 128 + (((uint32_t)(s * 32 + b_col_off)) ^ sw));
#pragma unroll
                    for (int mt = 0; mt < 2; mt++) {
                        mma16816h(acc2[mt][2 * np],     ah[mt], bh[0], bh[1]);
                        mma16816h(acc2[mt][2 * np + 1], ah[mt], bh[2], bh[3]);
                    }
                }
            }
            __syncthreads();
        }

        // prefetch next q's GEMM1 step 0
        if (q < P_ - 1) { issue_g1(sb, 0, t, qb + B_, pb, j0, 0, 0); cp_commit(); }
    }

    // ===================== final epilogue: pure store ========================
    {
        float* ob = out + (size_t)pb * 65536 + j0 + 64 * wj2;
#pragma unroll
        for (int mt = 0; mt < 2; mt++) {
#pragma unroll
            for (int h = 0; h < 2; h++) {
                const int c = 32 * wc + 16 * mt + 8 * h + (lane >> 2);
                float* rowp = ob + (size_t)c * 256;
#pragma unroll
                for (int nt = 0; nt < 8; nt++) {
                    float2 o;
                    o.x = acc2[mt][nt][2 * h] * invp;
                    o.y = acc2[mt][nt][2 * h + 1] * invp;
                    *(float2*)(rowp + nt * 8 + (lane & 3) * 2) = o;
                }
            }
        }
    }
}

// ---------------------------------------------------------------------------
extern "C" void kernel_launch(void* const* d_in, const int* in_sizes, int n_in,
                              void* d_out, int out_size) {
    const float* temp = (const float*)d_in[0];
    const float* We   = (const float*)d_in[1];
    const float* Wg   = (const float*)d_in[2];
    const void*  pn   = (n_in > 3) ? d_in[3] : nullptr;
    float* out = (float*)d_out;

    transpose_split<<<dim3(8, 8, 64), 256>>>(temp);   // + fp16 copy fused in
    split_We<<<64, 256>>>(We);
    zero_wtf<<<16, 1024>>>();
    wtf_part<<<dim3(64, 8), 256>>>(temp, Wg);

    cudaFuncSetAttribute(corr_mma, cudaFuncAttributeMaxDynamicSharedMemorySize, 2 * STGC);
    corr_mma<<<dim3(2, 64), 512, 2 * STGC>>>();

    cudaFuncSetAttribute(fused_mma, cudaFuncAttributeMaxDynamicSharedMemorySize, SMEM_TOTAL);
    fused_mma<<<128, NT, SMEM_TOTAL>>>(pn, out);
}

// round 16
// speedup vs baseline: 1.3862x; 1.0468x over previous
#include <cuda_runtime.h>
#include <cuda_bf16.h>
#include <cuda_fp16.h>
#include <cstdint>

#define P_ 16
#define B_ 4
#define C_ 256
#define N_ 256
#define PB_ 64

typedef __nv_bfloat16 bf16;

// ---------------- gmem scratch ----------------
__device__ __align__(16) bf16  g_corr_h[(size_t)PB_ * N_ * C_];  // corr split [pb][j][d]
__device__ __align__(16) bf16  g_corr_l[(size_t)PB_ * N_ * C_];
__device__ __align__(16) unsigned short g_tf_f16[(size_t)PB_ * C_ * N_];  // temp fp16 [pb][c][i]
__device__ __align__(16) bf16  g_tfT_h[(size_t)PB_ * N_ * C_];   // temp^T split [pb][i][c]
__device__ __align__(16) bf16  g_tfT_l[(size_t)PB_ * N_ * C_];
__device__ __align__(16) bf16  g_We_h[(size_t)C_ * C_];          // We split [d][c]
__device__ __align__(16) bf16  g_We_l[(size_t)C_ * C_];
__device__ __align__(16) float g_wtf[(size_t)PB_ * N_];

// ---------------- helpers ----------------
__device__ __forceinline__ uint32_t smem_u32(const void* p) {
    uint32_t a;
    asm("{ .reg .u64 t; cvta.to.shared.u64 t, %1; cvt.u32.u64 %0, t; }" : "=r"(a) : "l"(p));
    return a;
}
__device__ __forceinline__ void ldm_x4(uint32_t& r0, uint32_t& r1, uint32_t& r2,
                                       uint32_t& r3, uint32_t a) {
    asm volatile("ldmatrix.sync.aligned.m8n8.x4.shared.b16 {%0,%1,%2,%3}, [%4];"
                 : "=r"(r0), "=r"(r1), "=r"(r2), "=r"(r3) : "r"(a));
}
__device__ __forceinline__ void mma16816(float* c, const uint32_t* a,
                                         uint32_t b0, uint32_t b1) {
    asm volatile("mma.sync.aligned.m16n8k16.row.col.f32.bf16.bf16.f32 "
                 "{%0,%1,%2,%3}, {%4,%5,%6,%7}, {%8,%9}, {%0,%1,%2,%3};"
                 : "+f"(c[0]), "+f"(c[1]), "+f"(c[2]), "+f"(c[3])
                 : "r"(a[0]), "r"(a[1]), "r"(a[2]), "r"(a[3]), "r"(b0), "r"(b1));
}
__device__ __forceinline__ void mma16816h(float* c, const uint32_t* a,
                                          uint32_t b0, uint32_t b1) {
    asm volatile("mma.sync.aligned.m16n8k16.row.col.f32.f16.f16.f32 "
                 "{%0,%1,%2,%3}, {%4,%5,%6,%7}, {%8,%9}, {%0,%1,%2,%3};"
                 : "+f"(c[0]), "+f"(c[1]), "+f"(c[2]), "+f"(c[3])
                 : "r"(a[0]), "r"(a[1]), "r"(a[2]), "r"(a[3]), "r"(b0), "r"(b1));
}
__device__ __forceinline__ uint32_t pack_f16(float lo, float hi) {
    uint32_t r;
    asm("cvt.rn.f16x2.f32 %0, %1, %2;" : "=r"(r) : "f"(hi), "f"(lo));
    return r;
}
__device__ __forceinline__ uint32_t pack2_bf16(bf16 lo, bf16 hi) {
    return ((uint32_t)__bfloat16_as_ushort(hi) << 16) | (uint32_t)__bfloat16_as_ushort(lo);
}
__device__ __forceinline__ void cpa16(uint32_t d, const void* s) {
    asm volatile("cp.async.cg.shared.global [%0], [%1], 16;" :: "r"(d), "l"(s));
}
__device__ __forceinline__ void cp_commit() {
    asm volatile("cp.async.commit_group;" ::: "memory");
}
__device__ __forceinline__ void cp_wait1() {
    asm volatile("cp.async.wait_group 1;" ::: "memory");
}
__device__ __forceinline__ void cp_wait0() {
    asm volatile("cp.async.wait_group 0;" ::: "memory");
}
__device__ __forceinline__ float inv_patch(const void* p) {
    if (p == nullptr) return 1.f / 16.f;
    int iv = *(const int*)p;
    if (iv >= 1 && iv <= 65536) return 1.f / (float)iv;
    float fv = __int_as_float(iv);
    if (fv >= 0.5f && fv <= 65536.f) return 1.f / fv;
    return 1.f / 16.f;
}

// ---------------------------------------------------------------------------
// Prep kernels (verified R15)
// ---------------------------------------------------------------------------
__device__ __forceinline__ void split4(const float4 x, uint2& uh, uint2& ul) {
    bf16 h0 = __float2bfloat16(x.x), h1 = __float2bfloat16(x.y);
    bf16 h2 = __float2bfloat16(x.z), h3 = __float2bfloat16(x.w);
    bf16 l0 = __float2bfloat16(x.x - __bfloat162float(h0));
    bf16 l1 = __float2bfloat16(x.y - __bfloat162float(h1));
    bf16 l2 = __float2bfloat16(x.z - __bfloat162float(h2));
    bf16 l3 = __float2bfloat16(x.w - __bfloat162float(h3));
    uh = make_uint2(pack2_bf16(h0, h1), pack2_bf16(h2, h3));
    ul = make_uint2(pack2_bf16(l0, l1), pack2_bf16(l2, l3));
}
__global__ void __launch_bounds__(256) split_We(const float* __restrict__ We) {
    size_t i = (size_t)blockIdx.x * 256 + threadIdx.x;
    float4 x = ((const float4*)We)[i];
    uint2 uh, ul;
    split4(x, uh, ul);
    ((uint2*)g_We_h)[i] = uh;
    ((uint2*)g_We_l)[i] = ul;
}
__global__ void __launch_bounds__(256) transpose_split(const float* __restrict__ temp) {
    __shared__ float tile[32][33];
    const int pb = blockIdx.z;
    const int i0 = blockIdx.x * 32, c0 = blockIdx.y * 32;
    const int tx = threadIdx.x & 31, ty = threadIdx.x >> 5;
    const float* src = temp + (size_t)pb * C_ * N_;
#pragma unroll
    for (int k = 0; k < 4; k++) {
        int c = c0 + ty + k * 8;
        float x = src[(size_t)c * N_ + i0 + tx];
        tile[ty + k * 8][tx] = x;
        g_tf_f16[(size_t)pb * 65536 + (size_t)c * N_ + i0 + tx] =
            __half_as_ushort(__float2half(x));
    }
    __syncthreads();
#pragma unroll
    for (int k = 0; k < 4; k++) {
        int i = i0 + ty + k * 8;
        float x = tile[tx][ty + k * 8];
        size_t o = (size_t)pb * N_ * C_ + (size_t)i * C_ + c0 + tx;
        bf16 hh = __float2bfloat16(x);
        g_tfT_h[o] = hh;
        g_tfT_l[o] = __float2bfloat16(x - __bfloat162float(hh));
    }
}
__global__ void __launch_bounds__(1024) zero_wtf() {
    g_wtf[blockIdx.x * 1024 + threadIdx.x] = 0.f;
}
__global__ void __launch_bounds__(256) wtf_part(const float* __restrict__ temp,
                                                const float* __restrict__ Wg) {
    __shared__ float sWg[32];
    const int pb = blockIdx.x, cc = blockIdx.y;
    const int i = threadIdx.x;
    if (i < 32) sWg[i] = Wg[cc * 32 + i];
    __syncthreads();
    const float* src = temp + (size_t)pb * C_ * N_ + (size_t)cc * 32 * N_;
    float s = 0.f;
#pragma unroll 8
    for (int c = 0; c < 32; c++) s += src[(size_t)c * N_ + i] * sWg[c];
    atomicAdd(&g_wtf[(size_t)pb * N_ + i], s);
}

// ---------------------------------------------------------------------------
// corr via mma (verified R14/15): corr[pb][i][d] = sum_c tfT[pb][i][c]*We[d][c]
// ---------------------------------------------------------------------------
#define STGC 49152

__device__ __forceinline__ void issue_cm(uint32_t sb, int buf, int t,
                                         int pb, int ih, int kc) {
    {
        const int row = t >> 1, half = t & 1;
        const bf16* src = (half ? g_We_l : g_We_h) + (size_t)row * 256 + (size_t)kc * 32;
        const uint32_t dst = sb + buf * STGC + row * 128;
        const uint32_t sw = (uint32_t)((row & 7) << 4);
#pragma unroll
        for (int v = 0; v < 4; v++)
            cpa16(dst + (((uint32_t)(half * 64 + v * 16)) ^ sw), src + v * 8);
    }
    {
#pragma unroll
        for (int u = 0; u < 2; u++) {
            const int idx = t * 2 + u;
            const int row = idx >> 3, v = idx & 7;
            const bf16* srcp = (v < 4 ? g_tfT_h : g_tfT_l) +
                               ((size_t)pb * 65536 + (size_t)(ih * 128 + row) * 256 +
                                (size_t)kc * 32 + (size_t)(v & 3) * 8);
            const uint32_t d = sb + buf * STGC + 32768 + row * 128 +
                               (((uint32_t)(v * 16)) ^ ((uint32_t)((row & 7) << 4)));
            cpa16(d, srcp);
        }
    }
}

__global__ void __launch_bounds__(512, 1)
corr_mma() {
    extern __shared__ char smd[];
    const uint32_t sb = smem_u32(smd);
    const int t = threadIdx.x;
    const int w = t >> 5, lane = t & 31;
    const int ih = blockIdx.x;
    const int pb = blockIdx.y;

    const int wj = w >> 1, wi = w & 1;
    const int a_row_off = ((lane >> 3) & 1) * 8 + (lane & 7);
    const int a_col_off = ((lane >> 4) & 1) * 16;
    const int b_row_off = ((lane >> 4) & 1) * 8 + (lane & 7);
    const int b_col_off = ((lane >> 3) & 1) * 16;

    float acc[16][4];
#pragma unroll
    for (int n = 0; n < 16; n++)
#pragma unroll
        for (int x = 0; x < 4; x++) acc[n][x] = 0.f;

    issue_cm(sb, 0, t, pb, ih, 0);
    cp_commit();

#pragma unroll 1
    for (int kc = 0; kc < 8; kc++) {
        if (kc < 7) { issue_cm(sb, (kc + 1) & 1, t, pb, ih, kc + 1); cp_commit(); }
        if (kc < 7) cp_wait1(); else cp_wait0();
        __syncthreads();
        const uint32_t bB = sb + (kc & 1) * STGC;
        const uint32_t bA = bB + 32768;
#pragma unroll
        for (int s = 0; s < 2; s++) {
            uint32_t ah[4], al[4];
            {
                const int ar = 16 * wj + a_row_off;
                const uint32_t sw = (uint32_t)((ar & 7) << 4);
                const uint32_t ad = bA + ar * 128;
                ldm_x4(ah[0], ah[1], ah[2], ah[3],
                       ad + (((uint32_t)(s * 32 + a_col_off)) ^ sw));
                ldm_x4(al[0], al[1], al[2], al[3],
                       ad + (((uint32_t)(64 + s * 32 + a_col_off)) ^ sw));
            }
#pragma unroll
            for (int np = 0; np < 8; np++) {
                const int br = 128 * wi + np * 16 + b_row_off;
                const uint32_t sw = (uint32_t)((br & 7) << 4);
                const uint32_t bd = bB + br * 128;
                uint32_t bh[4], bl[4];
                ldm_x4(bh[0], bh[1], bh[2], bh[3],
                       bd + (((uint32_t)(s * 32 + b_col_off)) ^ sw));
                ldm_x4(bl[0], bl[1], bl[2], bl[3],
                       bd + (((uint32_t)(64 + s * 32 + b_col_off)) ^ sw));
                float* e = acc[2 * np];
                float* o = acc[2 * np + 1];
                mma16816(e, ah, bh[0], bh[1]);
                mma16816(o, ah, bh[2], bh[3]);
                mma16816(e, ah, bl[0], bl[1]);
                mma16816(o, ah, bl[2], bl[3]);
                mma16816(e, al, bh[0], bh[1]);
                mma16816(o, al, bh[2], bh[3]);
            }
        }
        __syncthreads();
    }

    const int r1 = 16 * wj + (lane >> 2);
    const int r2 = r1 + 8;
#pragma unroll
    for (int nt = 0; nt < 16; nt++) {
        const int d = 128 * wi + nt * 8 + (lane & 3) * 2;
#pragma unroll
        for (int rr = 0; rr < 2; rr++) {
            const int i = ih * 128 + (rr ? r2 : r1);
            float x0 = acc[nt][rr * 2 + 0], x1 = acc[nt][rr * 2 + 1];
            bf16 h0 = __float2bfloat16(x0), h1 = __float2bfloat16(x1);
            bf16 l0 = __float2bfloat16(x0 - __bfloat162float(h0));
            bf16 l1 = __float2bfloat16(x1 - __bfloat162float(h1));
            const size_t o = (size_t)pb * 65536 + (size_t)i * 256 + d;
            *(uint32_t*)(g_corr_h + o) = pack2_bf16(h0, h1);
            *(uint32_t*)(g_corr_l + o) = pack2_bf16(l0, l1);
        }
    }
}

// ---------------------------------------------------------------------------
// Fused kernel. 128 CTAs, 512 threads. Minimal-barrier pipeline (1 sync/chunk).
// SMEM: [0,64K)   two 32K stage bufs
//       [64K,128K)  P fp16: 4 chunks x 16K  (disjoint from fp32 staging)
//       [128K,192K) fp32 raw-exp staging for GEMM1 pass 0 (2 x 32K)
//       [192K+]     sWtf 1K | sSum 1K | sG 1K
// ---------------------------------------------------------------------------
#define STG1B 32768
#define PF    65536
#define PF32  131072
#define SWTF  196608
#define SSUM  197632
#define SGG   198656
#define SMEM_TOTAL 199680
#define NT 512

__device__ __forceinline__ void issue_g1(uint32_t sb, int buf, int t,
                                         int qb, int pb, int j0, int pass, int kc) {
    {   // B: tfT rows [pass*128, +128), 32B per thread
        const int row = t >> 2, qtr = t & 3;
        const bf16* src = (qtr < 2 ? g_tfT_h : g_tfT_l) +
                          ((size_t)qb * 65536 + (size_t)(pass * 128 + row) * 256 +
                           (size_t)kc * 32 + (size_t)(qtr & 1) * 16);
        const uint32_t dst = sb + buf * STG1B + row * 128;
        const uint32_t sw = (uint32_t)((row & 7) << 4);
        const uint32_t base = (uint32_t)((qtr >= 2 ? 64 : 0) + (qtr & 1) * 32);
#pragma unroll
        for (int v = 0; v < 2; v++)
            cpa16(dst + ((base + v * 16) ^ sw), src + v * 8);
    }
    {   // A: corr rows j0..j0+127
#pragma unroll
        for (int u = 0; u < 2; u++) {
            const int idx = t * 2 + u;
            const int row = idx >> 3, v = idx & 7;
            const bf16* srcp = (v < 4 ? g_corr_h : g_corr_l) +
                               ((size_t)pb * 65536 + (size_t)(j0 + row) * 256 +
                                (size_t)kc * 32 + (size_t)(v & 3) * 8);
            const uint32_t d = sb + buf * STG1B + 16384 + row * 128 +
                               (((uint32_t)(v * 16)) ^ ((uint32_t)((row & 7) << 4)));
            cpa16(d, srcp);
        }
    }
}

__device__ __forceinline__ void issue_g2(uint32_t sb, int buf, int t, int qb, int kc) {
    const int row = t >> 1, half = t & 1;
    const unsigned short* src = g_tf_f16 + (size_t)qb * 65536 + (size_t)row * 256 +
                                (size_t)kc * 64 + (size_t)half * 32;
    const uint32_t dst = sb + buf * STG1B + row * 128;
    const uint32_t sw = (uint32_t)((row & 7) << 4);
#pragma unroll
    for (int v = 0; v < 4; v++)
        cpa16(dst + (((uint32_t)(half * 64 + v * 16)) ^ sw), src + v * 8);
}

__global__ void __launch_bounds__(NT, 1)
fused_mma(const void* __restrict__ pnp, float* __restrict__ out) {
    extern __shared__ char smd[];
    const uint32_t sb = smem_u32(smd);
    float* sWtf = (float*)(smd + SWTF);
    float* sSum = (float*)(smd + SSUM);   // [2][128]
    float* sG   = (float*)(smd + SGG);    // [2][128]

    const int t = threadIdx.x;
    const int w = t >> 5, lane = t & 31;
    const int jt = blockIdx.x & 1;
    const int pb = blockIdx.x >> 1;
    const int b = pb & 3;
    const int j0 = jt * 128;

    const int wj = w >> 1, wi = w & 1;      // GEMM1: 8 j-warps(16j) x 2 i-warps(64i/pass)
    const int wc = w >> 1, wj2 = w & 1;     // GEMM2: 8 c-warps(32c) x 2 j-warps(64j)
    const float invp = inv_patch(pnp);

    const int a_row_off = ((lane >> 3) & 1) * 8 + (lane & 7);
    const int a_col_off = ((lane >> 4) & 1) * 16;
    const int b_row_off = ((lane >> 4) & 1) * 8 + (lane & 7);
    const int b_col_off = ((lane >> 3) & 1) * 16;

    // persistent output accumulator (gated att summed over q)
    float acc2[2][8][4];
#pragma unroll
    for (int m = 0; m < 2; m++)
#pragma unroll
        for (int n = 0; n < 8; n++)
#pragma unroll
            for (int x = 0; x < 4; x++) acc2[m][n][x] = 0.f;

    issue_g1(sb, 0, t, 0 * B_ + b, pb, j0, 0, 0);
    cp_commit();

#pragma unroll 1
    for (int q = 0; q < P_; q++) {
        const int qb = q * B_ + b;
        if (t < 256) sWtf[t] = g_wtf[(size_t)qb * N_ + t];

        float srun1 = 0.f, grun1 = 0.f, srun2 = 0.f, grun2 = 0.f;
        float acc1[8][4];   // pass accumulator; after pass1 holds pass-1 exp

        // ===== GEMM1 in two i-passes: 128j x 128i per pass, bf16 3-term ======
#pragma unroll 1
        for (int pass = 0; pass < 2; pass++) {
#pragma unroll
            for (int n = 0; n < 8; n++)
#pragma unroll
                for (int x = 0; x < 4; x++) acc1[n][x] = 0.f;

#pragma unroll 1
            for (int kc = 0; kc < 8; kc++) {
                const int step = pass * 8 + kc;
                cp_wait0();
                __syncthreads();     // chunk ready + prior readers done
                if (step < 15) {
                    issue_g1(sb, (step + 1) & 1, t, qb, pb, j0,
                             (step + 1) >> 3, (step + 1) & 7);
                } else {
                    issue_g2(sb, 0, t, qb, 0);   // prefetch GEMM2 chunk 0
                }
                cp_commit();
                const uint32_t bB = sb + (step & 1) * STG1B;
                const uint32_t bA = bB + 16384;
#pragma unroll
                for (int s = 0; s < 2; s++) {
                    uint32_t ah[4], al[4];
                    {
                        const int ar = 16 * wj + a_row_off;
                        const uint32_t sw = (uint32_t)((ar & 7) << 4);
                        const uint32_t ad = bA + ar * 128;
                        ldm_x4(ah[0], ah[1], ah[2], ah[3],
                               ad + (((uint32_t)(s * 32 + a_col_off)) ^ sw));
                        ldm_x4(al[0], al[1], al[2], al[3],
                               ad + (((uint32_t)(64 + s * 32 + a_col_off)) ^ sw));
                    }
#pragma unroll
                    for (int np = 0; np < 4; np++) {
                        const int br = 64 * wi + np * 16 + b_row_off;
                        const uint32_t sw = (uint32_t)((br & 7) << 4);
                        const uint32_t bd = bB + br * 128;
                        uint32_t bh[4], bl[4];
                        ldm_x4(bh[0], bh[1], bh[2], bh[3],
                               bd + (((uint32_t)(s * 32 + b_col_off)) ^ sw));
                        ldm_x4(bl[0], bl[1], bl[2], bl[3],
                               bd + (((uint32_t)(64 + s * 32 + b_col_off)) ^ sw));
                        float* e = acc1[2 * np];
                        float* o = acc1[2 * np + 1];
                        mma16816(e, ah, bh[0], bh[1]);
                        mma16816(o, ah, bh[2], bh[3]);
                        mma16816(e, ah, bl[0], bl[1]);
                        mma16816(o, ah, bl[2], bl[3]);
                        mma16816(e, al, bh[0], bh[1]);
                        mma16816(o, al, bh[2], bh[3]);
                    }
                }
            }

            // exp + partial sums; pass0 -> fp32 staging (disjoint region),
            // pass1 -> keep exp in acc1 registers
            const int r1 = 16 * wj + (lane >> 2);
            const int r2 = r1 + 8;
            if (pass == 0) {
                char* base32 = smd + PF32 + wi * 32768;
#pragma unroll
                for (int nt = 0; nt < 8; nt++) {
                    const int col = 64 * wi + nt * 8 + (lane & 3) * 2;
                    float2 wv = *(float2*)&sWtf[col];
                    float e0 = __expf(acc1[nt][0] - 40.f);
                    float e1 = __expf(acc1[nt][1] - 40.f);
                    float e2 = __expf(acc1[nt][2] - 40.f);
                    float e3 = __expf(acc1[nt][3] - 40.f);
                    srun1 += e0 + e1; grun1 += e0 * wv.x + e1 * wv.y;
                    srun2 += e2 + e3; grun2 += e2 * wv.x + e3 * wv.y;
                    const uint32_t off32 = (uint32_t)(nt * 32 + (lane & 3) * 8);
                    *(float2*)(base32 + r1 * 256 + off32) = make_float2(e0, e1);
                    *(float2*)(base32 + r2 * 256 + off32) = make_float2(e2, e3);
                }
            } else {
#pragma unroll
                for (int nt = 0; nt < 8; nt++) {
                    const int col = 128 + 64 * wi + nt * 8 + (lane & 3) * 2;
                    float2 wv = *(float2*)&sWtf[col];
                    float e0 = __expf(acc1[nt][0] - 40.f);
                    float e1 = __expf(acc1[nt][1] - 40.f);
                    float e2 = __expf(acc1[nt][2] - 40.f);
                    float e3 = __expf(acc1[nt][3] - 40.f);
                    acc1[nt][0] = e0; acc1[nt][1] = e1;
                    acc1[nt][2] = e2; acc1[nt][3] = e3;
                    srun1 += e0 + e1; grun1 += e0 * wv.x + e1 * wv.y;
                    srun2 += e2 + e3; grun2 += e2 * wv.x + e3 * wv.y;
                }
            }
        }

        // ===== softmax finalize =============================================
        {
#pragma unroll
            for (int o = 1; o <= 2; o <<= 1) {
                srun1 += __shfl_xor_sync(0xffffffffu, srun1, o);
                grun1 += __shfl_xor_sync(0xffffffffu, grun1, o);
                srun2 += __shfl_xor_sync(0xffffffffu, srun2, o);
                grun2 += __shfl_xor_sync(0xffffffffu, grun2, o);
            }
            const int r1 = 16 * wj + (lane >> 2);
            const int r2 = r1 + 8;
            if ((lane & 3) == 0) {
                sSum[wi * 128 + r1] = srun1;  sG[wi * 128 + r1] = grun1;
                sSum[wi * 128 + r2] = srun2;  sG[wi * 128 + r2] = grun2;
            }
            __syncthreads();    // [S1] sums + all P-related smem published

            // own-row scales; write pass-1 exp directly as scaled fp16 (ch 2+wi)
            float sc[2];
#pragma unroll
            for (int h = 0; h < 2; h++) {
                const int r = r1 + 8 * h;
                const float tot = sSum[r] + sSum[128 + r];
                const float gt  = sG[r] + sG[128 + r];
                sc[h] = (1.f / (1.f + __expf(-gt / tot))) / tot;
            }
            {
                char* base = smd + PF + (2 + wi) * 16384;
                const uint32_t sw1 = (uint32_t)((r1 & 7) << 4);
                const uint32_t sw2 = (uint32_t)((r2 & 7) << 4);
#pragma unroll
                for (int nt = 0; nt < 8; nt++) {
                    const uint32_t off = (uint32_t)(nt * 16 + (lane & 3) * 4);
                    *(uint32_t*)(base + r1 * 128 + (off ^ sw1)) =
                        pack_f16(acc1[nt][0] * sc[0], acc1[nt][1] * sc[0]);
                    *(uint32_t*)(base + r2 * 128 + (off ^ sw2)) =
                        pack_f16(acc1[nt][2] * sc[1], acc1[nt][3] * sc[1]);
                }
            }
            // rescale pass-0 fp32 chunks (0,1) -> scaled fp16 (disjoint regions)
            {
                const int prow = t >> 2;
                const float ptot = sSum[prow] + sSum[128 + prow];
                const float pgt  = sG[prow] + sG[128 + prow];
                const float scv = (1.f / (1.f + __expf(-pgt / ptot))) / ptot;
                const uint32_t sw = (uint32_t)((prow & 7) << 4);
                const uint32_t cb2 = (uint32_t)((t & 3) * 32);
#pragma unroll
                for (int ch = 0; ch < 2; ch++) {
                    const float4* src = (const float4*)(smd + PF32 + ch * 32768 + t * 64);
                    float4 a0 = src[0], a1 = src[1], a2 = src[2], a3 = src[3];
                    char* row = smd + PF + ch * 16384 + prow * 128;
                    *(uint32_t*)(row + ((cb2 + 0)  ^ sw)) = pack_f16(a0.x * scv, a0.y * scv);
                    *(uint32_t*)(row + ((cb2 + 4)  ^ sw)) = pack_f16(a0.z * scv, a0.w * scv);
                    *(uint32_t*)(row + ((cb2 + 8)  ^ sw)) = pack_f16(a1.x * scv, a1.y * scv);
                    *(uint32_t*)(row + ((cb2 + 12) ^ sw)) = pack_f16(a1.z * scv, a1.w * scv);
                    *(uint32_t*)(row + ((cb2 + 16) ^ sw)) = pack_f16(a2.x * scv, a2.y * scv);
                    *(uint32_t*)(row + ((cb2 + 20) ^ sw)) = pack_f16(a2.z * scv, a2.w * scv);
                    *(uint32_t*)(row + ((cb2 + 24) ^ sw)) = pack_f16(a3.x * scv, a3.y * scv);
                    *(uint32_t*)(row + ((cb2 + 28) ^ sw)) = pack_f16(a3.z * scv, a3.w * scv);
                }
            }
        }

        // ===== GEMM2: acc2 += tf_f16 . P'^T  (accumulates across q) ==========
#pragma unroll 1
        for (int kc = 0; kc < 4; kc++) {
            cp_wait0();
            __syncthreads();    // tf chunk ready + P writes/readers published
            if (kc < 3) {
                issue_g2(sb, (kc + 1) & 1, t, qb, kc + 1);
                cp_commit();
            } else if (q < P_ - 1) {
                issue_g1(sb, 0, t, qb + B_, pb, j0, 0, 0);
                cp_commit();
            }
            const uint32_t bA2 = sb + (kc & 1) * STG1B;
            const uint32_t pB = sb + PF + kc * 16384;
#pragma unroll
            for (int s = 0; s < 4; s++) {
                uint32_t ah[2][4];
#pragma unroll
                for (int mt = 0; mt < 2; mt++) {
                    const int ar = 32 * wc + 16 * mt + a_row_off;
                    const uint32_t sw = (uint32_t)((ar & 7) << 4);
                    ldm_x4(ah[mt][0], ah[mt][1], ah[mt][2], ah[mt][3],
                           bA2 + ar * 128 + (((uint32_t)(s * 32 + a_col_off)) ^ sw));
                }
#pragma unroll
                for (int np = 0; np < 4; np++) {
                    const int br = 64 * wj2 + np * 16 + b_row_off;
                    const uint32_t sw = (uint32_t)((br & 7) << 4);
                    uint32_t bh[4];
                    ldm_x4(bh[0], bh[1], bh[2], bh[3],
                           pB + br * 128 + (((uint32_t)(s * 32 + b_col_off)) ^ sw));
#pragma unroll
                    for (int mt = 0; mt < 2; mt++) {
                        mma16816h(acc2[mt][2 * np],     ah[mt], bh[0], bh[1]);
                        mma16816h(acc2[mt][2 * np + 1], ah[mt], bh[2], bh[3]);
                    }
                }
            }
        }
        __syncthreads();   // q-boundary: P region reused next q (exp writes)
    }

    // ===================== final epilogue: pure store ========================
    {
        float* ob = out + (size_t)pb * 65536 + j0 + 64 * wj2;
#pragma unroll
        for (int mt = 0; mt < 2; mt++) {
#pragma unroll
            for (int h = 0; h < 2; h++) {
                const int c = 32 * wc + 16 * mt + 8 * h + (lane >> 2);
                float* rowp = ob + (size_t)c * 256;
#pragma unroll
                for (int nt = 0; nt < 8; nt++) {
                    float2 o;
                    o.x = acc2[mt][nt][2 * h] * invp;
                    o.y = acc2[mt][nt][2 * h + 1] * invp;
                    *(float2*)(rowp + nt * 8 + (lane & 3) * 2) = o;
                }
            }
        }
    }
}

// ---------------------------------------------------------------------------
extern "C" void kernel_launch(void* const* d_in, const int* in_sizes, int n_in,
                              void* d_out, int out_size) {
    const float* temp = (const float*)d_in[0];
    const float* We   = (const float*)d_in[1];
    const float* Wg   = (const float*)d_in[2];
    const void*  pn   = (n_in > 3) ? d_in[3] : nullptr;
    float* out = (float*)d_out;

    transpose_split<<<dim3(8, 8, 64), 256>>>(temp);   // + fp16 copy fused in
    split_We<<<64, 256>>>(We);
    zero_wtf<<<16, 1024>>>();
    wtf_part<<<dim3(64, 8), 256>>>(temp, Wg);

    cudaFuncSetAttribute(corr_mma, cudaFuncAttributeMaxDynamicSharedMemorySize, 2 * STGC);
    corr_mma<<<dim3(2, 64), 512, 2 * STGC>>>();

    cudaFuncSetAttribute(fused_mma, cudaFuncAttributeMaxDynamicSharedMemorySize, SMEM_TOTAL);
    fused_mma<<<128, NT, SMEM_TOTAL>>>(pn, out);
}